// round 10
// baseline (speedup 1.0000x reference)
#include <cuda_runtime.h>
#include <cuda_fp16.h>
#include <cstdint>

// ---------------- problem constants ----------------
#define T_STEPS 10
#define B_SZ    8192
#define D_IN    1024
#define H1      512
#define H2      256
#define H3      128
#define N_OUT   10
#define M_TOT   (T_STEPS * B_SZ)                          // 81920
#define HALF_N  ((uint32_t)(T_STEPS * B_SZ * D_IN / 2))   // 41,943,040

// t-major rows: m = t*B + b
__device__ __half g_S   [(size_t)M_TOT * D_IN];           // 167 MB fp16 spikes
__device__ float  g_cur1[(size_t)M_TOT * H1];
__device__ __half g_s1  [(size_t)M_TOT * H1];
__device__ float  g_cur2[(size_t)M_TOT * H2];
__device__ __half g_s2  [(size_t)M_TOT * H2];
__device__ float  g_cur3[(size_t)M_TOT * H3];
__device__ float  g_s3sum[(size_t)B_SZ * H3];
__device__ __half g_W1s[2][(size_t)H1 * D_IN];
__device__ __half g_W2s[2][(size_t)H2 * H1];
__device__ __half g_W3s[2][(size_t)H3 * H2];

// ---------------- PTX helpers ----------------
__device__ __forceinline__ uint32_t smem_u32(const void* p) {
    uint32_t a;
    asm("{ .reg .u64 t; cvta.to.shared.u64 t, %1; cvt.u32.u64 %0, t; }" : "=r"(a) : "l"(p));
    return a;
}
__device__ __forceinline__ void cp16(uint32_t dst, const void* src) {
    asm volatile("cp.async.cg.shared.global [%0], [%1], 16;" :: "r"(dst), "l"(src) : "memory");
}
__device__ __forceinline__ void cp_commit() { asm volatile("cp.async.commit_group;" ::: "memory"); }
template<int N> __device__ __forceinline__ void cp_wait() {
    asm volatile("cp.async.wait_group %0;" :: "n"(N) : "memory");
}
__device__ __forceinline__ void ldsm4(uint32_t* r, uint32_t addr) {
    asm volatile("ldmatrix.sync.aligned.m8n8.x4.shared.b16 {%0,%1,%2,%3}, [%4];"
                 : "=r"(r[0]), "=r"(r[1]), "=r"(r[2]), "=r"(r[3]) : "r"(addr));
}
__device__ __forceinline__ void mma16816(float* d, const uint32_t* a, const uint32_t* b) {
    asm volatile(
        "mma.sync.aligned.m16n8k16.row.col.f32.f16.f16.f32 "
        "{%0,%1,%2,%3}, {%4,%5,%6,%7}, {%8,%9}, {%0,%1,%2,%3};"
        : "+f"(d[0]), "+f"(d[1]), "+f"(d[2]), "+f"(d[3])
        : "r"(a[0]), "r"(a[1]), "r"(a[2]), "r"(a[3]), "r"(b[0]), "r"(b[1]));
}

// ---------------- Threefry-2x32-20, key = (0, 42) ----------------
// Adds routed to the FMA pipe via IMAD (mad.lo by runtime-opaque 1) to relieve
// the ALU pipe (measured 86% busy: SHF+LOP3 are ALU-only, adds need not be).
__device__ __forceinline__ uint32_t rotl32(uint32_t v, int r) {
    return (v << r) | (v >> (32 - r));
}
__device__ __forceinline__ void tf_add(uint32_t& a, uint32_t b, uint32_t one) {
    asm("mad.lo.u32 %0, %0, %1, %2;" : "+r"(a) : "r"(one), "r"(b));
}
__device__ __forceinline__ void tf_round(uint32_t& x0, uint32_t& x1, int r, uint32_t one) {
    tf_add(x0, x1, one);
    x1 = rotl32(x1, r);
    x1 ^= x0;
}
__device__ __forceinline__ void threefry_0_42(uint32_t x0, uint32_t x1,
                                              uint32_t& y0, uint32_t& y1, uint32_t one) {
    const uint32_t k1 = 42u;
    const uint32_t k2 = 0x1BD11BDAu ^ 42u;
    // inject 0: x0 += 0; x1 += k1
    tf_add(x1, k1, one);
    tf_round(x0, x1, 13, one); tf_round(x0, x1, 15, one);
    tf_round(x0, x1, 26, one); tf_round(x0, x1, 6, one);
    tf_add(x0, k1, one); tf_add(x1, k2 + 1u, one);
    tf_round(x0, x1, 17, one); tf_round(x0, x1, 29, one);
    tf_round(x0, x1, 16, one); tf_round(x0, x1, 24, one);
    tf_add(x0, k2, one); tf_add(x1, 2u, one);                 // k0 = 0
    tf_round(x0, x1, 13, one); tf_round(x0, x1, 15, one);
    tf_round(x0, x1, 26, one); tf_round(x0, x1, 6, one);
    /* x0 += k0 (0) */ tf_add(x1, k1 + 3u, one);
    tf_round(x0, x1, 17, one); tf_round(x0, x1, 29, one);
    tf_round(x0, x1, 16, one); tf_round(x0, x1, 24, one);
    tf_add(x0, k1, one); tf_add(x1, k2 + 4u, one);
    tf_round(x0, x1, 13, one); tf_round(x0, x1, 15, one);
    tf_round(x0, x1, 26, one); tf_round(x0, x1, 6, one);
    tf_add(x0, k2, one); tf_add(x1, 5u, one);                 // k0 + 5
    y0 = x0; y1 = x1;
}
__device__ __forceinline__ float bits_to_unit(uint32_t bits) {
    return __uint_as_float((bits >> 9) | 0x3f800000u) - 1.0f;
}

__global__ void spikegen_kernel(const float* __restrict__ images,
                                unsigned short* __restrict__ S) {
    uint32_t i = blockIdx.x * 256u + threadIdx.x;
    if (i >= HALF_N) return;
    uint32_t one = blockDim.x >> 8;          // == 1, opaque to ptxas
    uint32_t y0, y1;
    threefry_0_42(i, i + HALF_N, y0, y1, one);
    float img = images[i & ((B_SZ * D_IN) - 1u)];
    S[i]          = (bits_to_unit(y0) < img) ? (unsigned short)0x3C00 : (unsigned short)0;
    S[i + HALF_N] = (bits_to_unit(y1) < img) ? (unsigned short)0x3C00 : (unsigned short)0;
}

// ---------------- weight 2-way fp16 split (scaled residual) ----------------
// w ≈ wa + 2^-11 * wb; error ≤ 2^-23*|w|.
__global__ void split_w_kernel(const float* __restrict__ W, __half* __restrict__ a,
                               __half* __restrict__ b, int n) {
    int i = blockIdx.x * 256 + threadIdx.x;
    if (i >= n) return;
    float w = W[i];
    __half h = __float2half(w);
    float r = w - __half2float(h);
    a[i] = h;
    b[i] = __float2half(r * 2048.0f);
}

// ---------------- persistent mma.sync GEMM: C = A @ (Wa + 2^-11*Wb)^T + bias ----
// BM=128, BN=128, BK=64, 2 stages, 1 barrier per chunk, 256 threads (8 warps,
// 2x4), warp tile m64 x n32, persistent CTAs with cross-tile chunk-0 prefetch.
#define ROWB 144
#define A_SZ   (128 * ROWB)                 // 18432 B
#define W_SZ   (128 * ROWB)                 // 18432 B
#define STAGE_SZ (A_SZ + 2 * W_SZ)          // 55296 B
#define GEMM_SMEM (2 * STAGE_SZ)            // 110592 B

__device__ __forceinline__ void load_chunk(
    const __half* __restrict__ A, const __half* __restrict__ Wa,
    const __half* __restrict__ Wb, uint32_t sbase, int stage,
    int m0, int n0, int K, int c, int tid)
{
    uint32_t st = sbase + stage * STAGE_SZ;
    const int k0 = c * 64;
    const __half* Ab = A + (size_t)m0 * K + k0;
#pragma unroll
    for (int i = 0; i < 4; i++) {
        int idx = i * 256 + tid;
        int row = idx >> 3, q = idx & 7;
        cp16(st + (uint32_t)(row * ROWB + q * 16), Ab + (size_t)row * K + q * 8);
    }
    const __half* const Ws[2] = {Wa, Wb};
#pragma unroll
    for (int s = 0; s < 2; s++) {
        const __half* Wp = Ws[s] + (size_t)n0 * K + k0;
        uint32_t bs = st + A_SZ + s * W_SZ;
#pragma unroll
        for (int i = 0; i < 4; i++) {
            int idx = i * 256 + tid;
            int row = idx >> 3, q = idx & 7;
            cp16(bs + (uint32_t)(row * ROWB + q * 16), Wp + (size_t)row * K + q * 8);
        }
    }
    cp_commit();
}

__global__ __launch_bounds__(256, 2)
void gemm_mma(const __half* __restrict__ A,
              const __half* __restrict__ Wa,
              const __half* __restrict__ Wb,
              const float* __restrict__ bias,
              float* __restrict__ C, int N, int K, int ntiles, int nx)
{
    extern __shared__ char smem[];
    const uint32_t sbase = smem_u32(smem);
    const int tid  = threadIdx.x;
    const int warp = tid >> 5;
    const int lane = tid & 31;
    const int wm = warp >> 2;                 // m offset wm*64
    const int wn = warp & 3;                  // n offset wn*32
    const int NC = K >> 6;

    const uint32_t a_row = (uint32_t)(lane & 15) * ROWB;
    const uint32_t a_col = (uint32_t)(lane >> 4) * 16;
    const uint32_t b_row = (uint32_t)((lane & 7) + ((lane >> 4) & 1) * 8) * ROWB;
    const uint32_t b_col = (uint32_t)((lane >> 3) & 1) * 16;
    const __half2 sc2 = __half2half2(__ushort_as_half((unsigned short)0x1000)); // 2^-11

    int g = 0;          // global chunk counter -> stage = g & 1
    bool first = true;

    for (int tile = blockIdx.x; tile < ntiles; tile += gridDim.x) {
        const int m0 = (tile / nx) * 128;
        const int n0 = (tile % nx) * 128;

        float acc[4][4][4];
#pragma unroll
        for (int mt = 0; mt < 4; mt++)
#pragma unroll
            for (int nt = 0; nt < 4; nt++)
#pragma unroll
                for (int r = 0; r < 4; r++) acc[mt][nt][r] = 0.0f;

        if (first) {                  // very first chunk of this CTA
            load_chunk(A, Wa, Wb, sbase, g & 1, m0, n0, K, 0, tid);
            first = false;
        }

        for (int c = 0; c < NC; c++) {
            cp_wait<0>();             // chunk g resident
            __syncthreads();          // all reads of stage (g+1)&1 (prev iter) done
            if (c + 1 < NC) {
                load_chunk(A, Wa, Wb, sbase, (g + 1) & 1, m0, n0, K, c + 1, tid);
            } else {
                int nt2 = tile + gridDim.x;      // prefetch next tile's chunk 0
                if (nt2 < ntiles)
                    load_chunk(A, Wa, Wb, sbase, (g + 1) & 1,
                               (nt2 / nx) * 128, (nt2 % nx) * 128, K, 0, tid);
            }

            uint32_t st = sbase + (g & 1) * STAGE_SZ;
#pragma unroll
            for (int ks = 0; ks < 4; ks++) {
                // all loads upfront: 4 A-ldsm + 4 B-ldsm (both terms)
                uint32_t a[4][4];
#pragma unroll
                for (int mt = 0; mt < 4; mt++) {
                    uint32_t addr = st + (uint32_t)(wm * 64 + mt * 16) * ROWB + a_row
                                  + (uint32_t)ks * 32 + a_col;
                    ldsm4(a[mt], addr);
                }
                uint32_t b0[4][2], b1[4][2];
#pragma unroll
                for (int p = 0; p < 2; p++) {
                    uint32_t addr0 = st + A_SZ
                                   + (uint32_t)(wn * 32 + p * 16) * ROWB + b_row
                                   + (uint32_t)ks * 32 + b_col;
                    uint32_t r[4];
                    ldsm4(r, addr0);
                    b0[p * 2 + 0][0] = r[0]; b0[p * 2 + 0][1] = r[1];
                    b0[p * 2 + 1][0] = r[2]; b0[p * 2 + 1][1] = r[3];
                    ldsm4(r, addr0 + W_SZ);
                    b1[p * 2 + 0][0] = r[0]; b1[p * 2 + 0][1] = r[1];
                    b1[p * 2 + 1][0] = r[2]; b1[p * 2 + 1][1] = r[3];
                }
                // term 0: A @ Wa
#pragma unroll
                for (int mt = 0; mt < 4; mt++)
#pragma unroll
                    for (int nt = 0; nt < 4; nt++)
                        mma16816(acc[mt][nt], a[mt], b0[nt]);
                // scale A fragment: spikes 1 -> 2^-11 (exact)
#pragma unroll
                for (int mt = 0; mt < 4; mt++)
#pragma unroll
                    for (int j = 0; j < 4; j++) {
                        __half2 v = *(__half2*)&a[mt][j];
                        v = __hmul2(v, sc2);
                        a[mt][j] = *(uint32_t*)&v;
                    }
                // term 1: (2^-11 A) @ Wb
#pragma unroll
                for (int mt = 0; mt < 4; mt++)
#pragma unroll
                    for (int nt = 0; nt < 4; nt++)
                        mma16816(acc[mt][nt], a[mt], b1[nt]);
            }
            g++;
        }

        // epilogue (+bias, fp32) — overlaps the prefetched next-tile chunk-0 load
#pragma unroll
        for (int nt = 0; nt < 4; nt++) {
            const int ccol = n0 + wn * 32 + nt * 8 + (lane & 3) * 2;
            const float bz0 = __ldg(&bias[ccol]);
            const float bz1 = __ldg(&bias[ccol + 1]);
#pragma unroll
            for (int mt = 0; mt < 4; mt++) {
                const int r0 = m0 + wm * 64 + mt * 16 + (lane >> 2);
                float2 v0 = make_float2(acc[mt][nt][0] + bz0, acc[mt][nt][1] + bz1);
                float2 v1 = make_float2(acc[mt][nt][2] + bz0, acc[mt][nt][3] + bz1);
                *(float2*)(C + (size_t)r0 * N + ccol)       = v0;
                *(float2*)(C + (size_t)(r0 + 8) * N + ccol) = v1;
            }
        }
    }
}

// ---------------- LIF scan (exact op order), fp16 spike out ----------------
__global__ void lif_kernel(const float* __restrict__ CUR, __half* __restrict__ S, int NBH) {
    int i = blockIdx.x * 256 + threadIdx.x;
    if (i >= NBH) return;
    float mem = 0.0f;
#pragma unroll
    for (int t = 0; t < T_STEPS; t++) {
        float cur = CUR[(size_t)t * NBH + i];
        float r = (mem > 1.0f) ? 1.0f : 0.0f;
        mem = __fmul_rn(0.9f, mem);
        mem = __fadd_rn(mem, cur);
        mem = __fsub_rn(mem, r);
        S[(size_t)t * NBH + i] =
            __float2half((__fsub_rn(mem, 1.0f) > 0.0f) ? 1.0f : 0.0f);
    }
}
__global__ void lif_sum_kernel(const float* __restrict__ CUR, float* __restrict__ Ssum, int NBH) {
    int i = blockIdx.x * 256 + threadIdx.x;
    if (i >= NBH) return;
    float mem = 0.0f, s = 0.0f;
#pragma unroll
    for (int t = 0; t < T_STEPS; t++) {
        float cur = CUR[(size_t)t * NBH + i];
        float r = (mem > 1.0f) ? 1.0f : 0.0f;
        mem = __fmul_rn(0.9f, mem);
        mem = __fadd_rn(mem, cur);
        mem = __fsub_rn(mem, r);
        if (__fsub_rn(mem, 1.0f) > 0.0f) s += 1.0f;
    }
    Ssum[i] = s;
}

// ---------------- head: Z = S3sum @ W4^T + 10*b4, softmax ----------------
__global__ void head_kernel(const float* __restrict__ S3sum, const float* __restrict__ W4,
                            const float* __restrict__ b4, float* __restrict__ out) {
    int b = blockIdx.x * 256 + threadIdx.x;
    if (b >= B_SZ) return;
    float acc[N_OUT];
#pragma unroll
    for (int c = 0; c < N_OUT; c++) acc[c] = 10.0f * b4[c];
    const float* row = S3sum + (size_t)b * H3;
#pragma unroll 4
    for (int j = 0; j < H3; j++) {
        float x = row[j];
        if (x != 0.0f) {
#pragma unroll
            for (int c = 0; c < N_OUT; c++) acc[c] += x * __ldg(&W4[c * H3 + j]);
        }
    }
    float m = acc[0];
#pragma unroll
    for (int c = 1; c < N_OUT; c++) m = fmaxf(m, acc[c]);
    float sum = 0.0f, e[N_OUT];
#pragma unroll
    for (int c = 0; c < N_OUT; c++) { e[c] = expf(acc[c] - m); sum += e[c]; }
    float inv = 1.0f / sum;
#pragma unroll
    for (int c = 0; c < N_OUT; c++) out[(size_t)b * N_OUT + c] = e[c] * inv;
}

// ---------------- launch ----------------
extern "C" void kernel_launch(void* const* d_in, const int* in_sizes, int n_in,
                              void* d_out, int out_size) {
    const float* images = (const float*)d_in[0];
    const float* W1 = (const float*)d_in[1];
    const float* b1 = (const float*)d_in[2];
    const float* W2 = (const float*)d_in[3];
    const float* b2 = (const float*)d_in[4];
    const float* W3 = (const float*)d_in[5];
    const float* b3 = (const float*)d_in[6];
    const float* W4 = (const float*)d_in[7];
    const float* b4 = (const float*)d_in[8];
    float* out = (float*)d_out;

    __half *S, *s1, *s2, *W1s, *W2s, *W3s;
    float *cur1, *cur2, *cur3, *s3sum;
    cudaGetSymbolAddress((void**)&S,     g_S);
    cudaGetSymbolAddress((void**)&cur1,  g_cur1);
    cudaGetSymbolAddress((void**)&s1,    g_s1);
    cudaGetSymbolAddress((void**)&cur2,  g_cur2);
    cudaGetSymbolAddress((void**)&s2,    g_s2);
    cudaGetSymbolAddress((void**)&cur3,  g_cur3);
    cudaGetSymbolAddress((void**)&s3sum, g_s3sum);
    cudaGetSymbolAddress((void**)&W1s,   g_W1s);
    cudaGetSymbolAddress((void**)&W2s,   g_W2s);
    cudaGetSymbolAddress((void**)&W3s,   g_W3s);

    cudaFuncSetAttribute(gemm_mma, cudaFuncAttributeMaxDynamicSharedMemorySize, GEMM_SMEM);

    int sms = 148;
    cudaDeviceGetAttribute(&sms, cudaDevAttrMultiProcessorCount, 0);
    const int pb = sms * 2;                  // persistent CTAs (2 per SM)

    const size_t n1 = (size_t)H1 * D_IN, n2 = (size_t)H2 * H1, n3 = (size_t)H3 * H2;
    split_w_kernel<<<(int)((n1 + 255) / 256), 256>>>(W1, W1s, W1s + n1, (int)n1);
    split_w_kernel<<<(int)((n2 + 255) / 256), 256>>>(W2, W2s, W2s + n2, (int)n2);
    split_w_kernel<<<(int)((n3 + 255) / 256), 256>>>(W3, W3s, W3s + n3, (int)n3);

    spikegen_kernel<<<(HALF_N + 255) / 256, 256>>>(images, (unsigned short*)S);

    const int nt1 = (M_TOT / 128) * (H1 / 128);   // 2560
    gemm_mma<<<(nt1 < pb ? nt1 : pb), 256, GEMM_SMEM>>>(
        S, W1s, W1s + n1, b1, cur1, H1, D_IN, nt1, H1 / 128);
    lif_kernel<<<(B_SZ * H1 + 255) / 256, 256>>>(cur1, s1, B_SZ * H1);

    const int nt2 = (M_TOT / 128) * (H2 / 128);   // 1280
    gemm_mma<<<(nt2 < pb ? nt2 : pb), 256, GEMM_SMEM>>>(
        s1, W2s, W2s + n2, b2, cur2, H2, H1, nt2, H2 / 128);
    lif_kernel<<<(B_SZ * H2 + 255) / 256, 256>>>(cur2, s2, B_SZ * H2);

    const int nt3 = (M_TOT / 128) * (H3 / 128);   // 640
    gemm_mma<<<(nt3 < pb ? nt3 : pb), 256, GEMM_SMEM>>>(
        s2, W3s, W3s + n3, b3, cur3, H3, H2, nt3, H3 / 128);
    lif_sum_kernel<<<(B_SZ * H3 + 255) / 256, 256>>>(cur3, s3sum, B_SZ * H3);

    head_kernel<<<(B_SZ + 255) / 256, 256>>>(s3sum, W4, b4, out);
}

// round 11
// speedup vs baseline: 1.0110x; 1.0110x over previous
#include <cuda_runtime.h>
#include <cuda_fp16.h>
#include <cstdint>

// ---------------- problem constants ----------------
#define T_STEPS 10
#define B_SZ    8192
#define D_IN    1024
#define H1      512
#define H2      256
#define H3      128
#define N_OUT   10
#define M_TOT   (T_STEPS * B_SZ)                          // 81920
#define HALF_N  ((uint32_t)(T_STEPS * B_SZ * D_IN / 2))   // 41,943,040

// t-major rows: m = t*B + b
__device__ __half g_S   [(size_t)M_TOT * D_IN];           // 167 MB fp16 spikes
__device__ float  g_cur1[(size_t)M_TOT * H1];
__device__ __half g_s1  [(size_t)M_TOT * H1];
__device__ float  g_cur2[(size_t)M_TOT * H2];
__device__ __half g_s2  [(size_t)M_TOT * H2];
__device__ float  g_cur3[(size_t)M_TOT * H3];
__device__ float  g_s3sum[(size_t)B_SZ * H3];
__device__ __half g_W1s[2][(size_t)H1 * D_IN];
__device__ __half g_W2s[2][(size_t)H2 * H1];
__device__ __half g_W3s[2][(size_t)H3 * H2];

// ---------------- PTX helpers ----------------
__device__ __forceinline__ uint32_t smem_u32(const void* p) {
    uint32_t a;
    asm("{ .reg .u64 t; cvta.to.shared.u64 t, %1; cvt.u32.u64 %0, t; }" : "=r"(a) : "l"(p));
    return a;
}
__device__ __forceinline__ void cp16(uint32_t dst, const void* src) {
    asm volatile("cp.async.cg.shared.global [%0], [%1], 16;" :: "r"(dst), "l"(src) : "memory");
}
__device__ __forceinline__ void cp_commit() { asm volatile("cp.async.commit_group;" ::: "memory"); }
template<int N> __device__ __forceinline__ void cp_wait() {
    asm volatile("cp.async.wait_group %0;" :: "n"(N) : "memory");
}
__device__ __forceinline__ void ldsm4(uint32_t* r, uint32_t addr) {
    asm volatile("ldmatrix.sync.aligned.m8n8.x4.shared.b16 {%0,%1,%2,%3}, [%4];"
                 : "=r"(r[0]), "=r"(r[1]), "=r"(r[2]), "=r"(r[3]) : "r"(addr));
}
__device__ __forceinline__ void mma16816(float* d, const uint32_t* a, const uint32_t* b) {
    asm volatile(
        "mma.sync.aligned.m16n8k16.row.col.f32.f16.f16.f32 "
        "{%0,%1,%2,%3}, {%4,%5,%6,%7}, {%8,%9}, {%0,%1,%2,%3};"
        : "+f"(d[0]), "+f"(d[1]), "+f"(d[2]), "+f"(d[3])
        : "r"(a[0]), "r"(a[1]), "r"(a[2]), "r"(a[3]), "r"(b[0]), "r"(b[1]));
}

// ---------------- Threefry-2x32-20, key = (0, 42) ----------------
__device__ __forceinline__ uint32_t rotl32(uint32_t v, int r) {
    return (v << r) | (v >> (32 - r));
}
__device__ __forceinline__ void threefry_0_42(uint32_t x0, uint32_t x1,
                                              uint32_t& y0, uint32_t& y1) {
    const uint32_t k0 = 0u, k1 = 42u;
    const uint32_t k2 = k0 ^ k1 ^ 0x1BD11BDAu;
    x0 += k0; x1 += k1;
#define TF_RND(r) { x0 += x1; x1 = rotl32(x1, r); x1 ^= x0; }
    TF_RND(13) TF_RND(15) TF_RND(26) TF_RND(6)
    x0 += k1; x1 += k2 + 1u;
    TF_RND(17) TF_RND(29) TF_RND(16) TF_RND(24)
    x0 += k2; x1 += k0 + 2u;
    TF_RND(13) TF_RND(15) TF_RND(26) TF_RND(6)
    x0 += k0; x1 += k1 + 3u;
    TF_RND(17) TF_RND(29) TF_RND(16) TF_RND(24)
    x0 += k1; x1 += k2 + 4u;
    TF_RND(13) TF_RND(15) TF_RND(26) TF_RND(6)
    x0 += k2; x1 += k0 + 5u;
#undef TF_RND
    y0 = x0; y1 = x1;
}
__device__ __forceinline__ float bits_to_unit(uint32_t bits) {
    return __uint_as_float((bits >> 9) | 0x3f800000u) - 1.0f;
}

__global__ void spikegen_kernel(const float* __restrict__ images, __half* __restrict__ S) {
    uint32_t i = blockIdx.x * 256u + threadIdx.x;
    if (i >= HALF_N) return;
    uint32_t y0, y1;
    threefry_0_42(i, i + HALF_N, y0, y1);
    float img = images[i & ((B_SZ * D_IN) - 1u)];
    S[i]          = __float2half((bits_to_unit(y0) < img) ? 1.0f : 0.0f);
    S[i + HALF_N] = __float2half((bits_to_unit(y1) < img) ? 1.0f : 0.0f);
}

// ---------------- weight 2-way fp16 split (scaled residual) ----------------
// w ≈ wa + 2^-11 * wb; error ≤ 2^-23*|w|.
__global__ void split_w_kernel(const float* __restrict__ W, __half* __restrict__ a,
                               __half* __restrict__ b, int n) {
    int i = blockIdx.x * 256 + threadIdx.x;
    if (i >= n) return;
    float w = W[i];
    __half h = __float2half(w);
    float r = w - __half2float(h);
    a[i] = h;
    b[i] = __float2half(r * 2048.0f);
}

// ---------------- persistent mma.sync GEMM: C = A @ (Wa + 2^-11*Wb)^T + bias ----
// BM=128, BN=128, BK=64, 2 stages, 1 barrier per chunk, 256 threads (8 warps,
// 2x4), warp tile m64 x n32. R9 inner loop (transient B fragments — stays
// under the 128-reg cap); persistent CTAs + cross-tile chunk-0 prefetch only.
#define ROWB 144
#define A_SZ   (128 * ROWB)                 // 18432 B
#define W_SZ   (128 * ROWB)                 // 18432 B
#define STAGE_SZ (A_SZ + 2 * W_SZ)          // 55296 B
#define GEMM_SMEM (2 * STAGE_SZ)            // 110592 B

__device__ __forceinline__ void load_chunk(
    const __half* __restrict__ A, const __half* __restrict__ Wa,
    const __half* __restrict__ Wb, uint32_t sbase, int stage,
    int m0, int n0, int K, int c, int tid)
{
    uint32_t st = sbase + stage * STAGE_SZ;
    const int k0 = c * 64;
    const __half* Ab = A + (size_t)m0 * K + k0;
#pragma unroll
    for (int i = 0; i < 4; i++) {
        int idx = i * 256 + tid;
        int row = idx >> 3, q = idx & 7;
        cp16(st + (uint32_t)(row * ROWB + q * 16), Ab + (size_t)row * K + q * 8);
    }
    const __half* const Ws[2] = {Wa, Wb};
#pragma unroll
    for (int s = 0; s < 2; s++) {
        const __half* Wp = Ws[s] + (size_t)n0 * K + k0;
        uint32_t bs = st + A_SZ + s * W_SZ;
#pragma unroll
        for (int i = 0; i < 4; i++) {
            int idx = i * 256 + tid;
            int row = idx >> 3, q = idx & 7;
            cp16(bs + (uint32_t)(row * ROWB + q * 16), Wp + (size_t)row * K + q * 8);
        }
    }
    cp_commit();
}

__global__ __launch_bounds__(256, 2)
void gemm_mma(const __half* __restrict__ A,
              const __half* __restrict__ Wa,
              const __half* __restrict__ Wb,
              const float* __restrict__ bias,
              float* __restrict__ C, int N, int K, int ntiles, int nx)
{
    extern __shared__ char smem[];
    const uint32_t sbase = smem_u32(smem);
    const int tid  = threadIdx.x;
    const int warp = tid >> 5;
    const int lane = tid & 31;
    const int wm = warp >> 2;                 // m offset wm*64
    const int wn = warp & 3;                  // n offset wn*32
    const int NC = K >> 6;

    const uint32_t a_row = (uint32_t)(lane & 15) * ROWB;
    const uint32_t a_col = (uint32_t)(lane >> 4) * 16;
    const uint32_t b_row = (uint32_t)((lane & 7) + ((lane >> 4) & 1) * 8) * ROWB;
    const uint32_t b_col = (uint32_t)((lane >> 3) & 1) * 16;
    const __half2 sc2 = __half2half2(__ushort_as_half((unsigned short)0x1000)); // 2^-11

    int g = 0;              // global chunk counter -> stage = g & 1
    bool first = true;

    for (int tile = blockIdx.x; tile < ntiles; tile += gridDim.x) {
        const int m0 = (tile / nx) * 128;
        const int n0 = (tile % nx) * 128;

        float acc[4][4][4];
#pragma unroll
        for (int mt = 0; mt < 4; mt++)
#pragma unroll
            for (int nt = 0; nt < 4; nt++)
#pragma unroll
                for (int r = 0; r < 4; r++) acc[mt][nt][r] = 0.0f;

        if (first) {
            load_chunk(A, Wa, Wb, sbase, g & 1, m0, n0, K, 0, tid);
            first = false;
        }

        for (int c = 0; c < NC; c++) {
            cp_wait<0>();            // chunk g resident
            __syncthreads();         // all reads of stage (g+1)&1 (prev chunk) done
            if (c + 1 < NC) {
                load_chunk(A, Wa, Wb, sbase, (g + 1) & 1, m0, n0, K, c + 1, tid);
            } else {
                int nt2 = tile + gridDim.x;      // prefetch next tile's chunk 0
                if (nt2 < ntiles)
                    load_chunk(A, Wa, Wb, sbase, (g + 1) & 1,
                               (nt2 / nx) * 128, (nt2 % nx) * 128, K, 0, tid);
            }

            uint32_t st = sbase + (g & 1) * STAGE_SZ;
#pragma unroll
            for (int ks = 0; ks < 4; ks++) {
                uint32_t a[4][4];
#pragma unroll
                for (int mt = 0; mt < 4; mt++) {
                    uint32_t addr = st + (uint32_t)(wm * 64 + mt * 16) * ROWB + a_row
                                  + (uint32_t)ks * 32 + a_col;
                    ldsm4(a[mt], addr);
                }
                // ---- term 0: A @ Wa (transient B fragments) ----
                {
                    uint32_t bfr[4][2];
#pragma unroll
                    for (int p = 0; p < 2; p++) {
                        uint32_t addr = st + A_SZ
                                      + (uint32_t)(wn * 32 + p * 16) * ROWB + b_row
                                      + (uint32_t)ks * 32 + b_col;
                        uint32_t r[4];
                        ldsm4(r, addr);
                        bfr[p * 2 + 0][0] = r[0]; bfr[p * 2 + 0][1] = r[1];
                        bfr[p * 2 + 1][0] = r[2]; bfr[p * 2 + 1][1] = r[3];
                    }
#pragma unroll
                    for (int mt = 0; mt < 4; mt++)
#pragma unroll
                        for (int nt = 0; nt < 4; nt++)
                            mma16816(acc[mt][nt], a[mt], bfr[nt]);
                }
                // scale A fragment: spikes 1 -> 2^-11 (exact)
#pragma unroll
                for (int mt = 0; mt < 4; mt++)
#pragma unroll
                    for (int j = 0; j < 4; j++) {
                        __half2 v = *(__half2*)&a[mt][j];
                        v = __hmul2(v, sc2);
                        a[mt][j] = *(uint32_t*)&v;
                    }
                // ---- term 1: (2^-11 * A) @ Wb ----
                {
                    uint32_t bfr[4][2];
#pragma unroll
                    for (int p = 0; p < 2; p++) {
                        uint32_t addr = st + A_SZ + W_SZ
                                      + (uint32_t)(wn * 32 + p * 16) * ROWB + b_row
                                      + (uint32_t)ks * 32 + b_col;
                        uint32_t r[4];
                        ldsm4(r, addr);
                        bfr[p * 2 + 0][0] = r[0]; bfr[p * 2 + 0][1] = r[1];
                        bfr[p * 2 + 1][0] = r[2]; bfr[p * 2 + 1][1] = r[3];
                    }
#pragma unroll
                    for (int mt = 0; mt < 4; mt++)
#pragma unroll
                        for (int nt = 0; nt < 4; nt++)
                            mma16816(acc[mt][nt], a[mt], bfr[nt]);
                }
            }
            g++;
        }

        // epilogue (+bias, fp32) — overlaps the prefetched next-tile chunk-0 load
#pragma unroll
        for (int nt = 0; nt < 4; nt++) {
            const int ccol = n0 + wn * 32 + nt * 8 + (lane & 3) * 2;
            const float bz0 = __ldg(&bias[ccol]);
            const float bz1 = __ldg(&bias[ccol + 1]);
#pragma unroll
            for (int mt = 0; mt < 4; mt++) {
                const int r0 = m0 + wm * 64 + mt * 16 + (lane >> 2);
                float2 v0 = make_float2(acc[mt][nt][0] + bz0, acc[mt][nt][1] + bz1);
                float2 v1 = make_float2(acc[mt][nt][2] + bz0, acc[mt][nt][3] + bz1);
                *(float2*)(C + (size_t)r0 * N + ccol)       = v0;
                *(float2*)(C + (size_t)(r0 + 8) * N + ccol) = v1;
            }
        }
    }
}

// ---------------- LIF scan (exact op order), fp16 spike out ----------------
__global__ void lif_kernel(const float* __restrict__ CUR, __half* __restrict__ S, int NBH) {
    int i = blockIdx.x * 256 + threadIdx.x;
    if (i >= NBH) return;
    float mem = 0.0f;
#pragma unroll
    for (int t = 0; t < T_STEPS; t++) {
        float cur = CUR[(size_t)t * NBH + i];
        float r = (mem > 1.0f) ? 1.0f : 0.0f;
        mem = __fmul_rn(0.9f, mem);
        mem = __fadd_rn(mem, cur);
        mem = __fsub_rn(mem, r);
        S[(size_t)t * NBH + i] =
            __float2half((__fsub_rn(mem, 1.0f) > 0.0f) ? 1.0f : 0.0f);
    }
}
__global__ void lif_sum_kernel(const float* __restrict__ CUR, float* __restrict__ Ssum, int NBH) {
    int i = blockIdx.x * 256 + threadIdx.x;
    if (i >= NBH) return;
    float mem = 0.0f, s = 0.0f;
#pragma unroll
    for (int t = 0; t < T_STEPS; t++) {
        float cur = CUR[(size_t)t * NBH + i];
        float r = (mem > 1.0f) ? 1.0f : 0.0f;
        mem = __fmul_rn(0.9f, mem);
        mem = __fadd_rn(mem, cur);
        mem = __fsub_rn(mem, r);
        if (__fsub_rn(mem, 1.0f) > 0.0f) s += 1.0f;
    }
    Ssum[i] = s;
}

// ---------------- head: Z = S3sum @ W4^T + 10*b4, softmax ----------------
__global__ void head_kernel(const float* __restrict__ S3sum, const float* __restrict__ W4,
                            const float* __restrict__ b4, float* __restrict__ out) {
    int b = blockIdx.x * 256 + threadIdx.x;
    if (b >= B_SZ) return;
    float acc[N_OUT];
#pragma unroll
    for (int c = 0; c < N_OUT; c++) acc[c] = 10.0f * b4[c];
    const float* row = S3sum + (size_t)b * H3;
#pragma unroll 4
    for (int j = 0; j < H3; j++) {
        float x = row[j];
        if (x != 0.0f) {
#pragma unroll
            for (int c = 0; c < N_OUT; c++) acc[c] += x * __ldg(&W4[c * H3 + j]);
        }
    }
    float m = acc[0];
#pragma unroll
    for (int c = 1; c < N_OUT; c++) m = fmaxf(m, acc[c]);
    float sum = 0.0f, e[N_OUT];
#pragma unroll
    for (int c = 0; c < N_OUT; c++) { e[c] = expf(acc[c] - m); sum += e[c]; }
    float inv = 1.0f / sum;
#pragma unroll
    for (int c = 0; c < N_OUT; c++) out[(size_t)b * N_OUT + c] = e[c] * inv;
}

// ---------------- launch ----------------
extern "C" void kernel_launch(void* const* d_in, const int* in_sizes, int n_in,
                              void* d_out, int out_size) {
    const float* images = (const float*)d_in[0];
    const float* W1 = (const float*)d_in[1];
    const float* b1 = (const float*)d_in[2];
    const float* W2 = (const float*)d_in[3];
    const float* b2 = (const float*)d_in[4];
    const float* W3 = (const float*)d_in[5];
    const float* b3 = (const float*)d_in[6];
    const float* W4 = (const float*)d_in[7];
    const float* b4 = (const float*)d_in[8];
    float* out = (float*)d_out;

    __half *S, *s1, *s2, *W1s, *W2s, *W3s;
    float *cur1, *cur2, *cur3, *s3sum;
    cudaGetSymbolAddress((void**)&S,     g_S);
    cudaGetSymbolAddress((void**)&cur1,  g_cur1);
    cudaGetSymbolAddress((void**)&s1,    g_s1);
    cudaGetSymbolAddress((void**)&cur2,  g_cur2);
    cudaGetSymbolAddress((void**)&s2,    g_s2);
    cudaGetSymbolAddress((void**)&cur3,  g_cur3);
    cudaGetSymbolAddress((void**)&s3sum, g_s3sum);
    cudaGetSymbolAddress((void**)&W1s,   g_W1s);
    cudaGetSymbolAddress((void**)&W2s,   g_W2s);
    cudaGetSymbolAddress((void**)&W3s,   g_W3s);

    cudaFuncSetAttribute(gemm_mma, cudaFuncAttributeMaxDynamicSharedMemorySize, GEMM_SMEM);

    int sms = 148;
    cudaDeviceGetAttribute(&sms, cudaDevAttrMultiProcessorCount, 0);
    const int pb = sms * 2;                  // persistent CTAs (2 per SM)

    const size_t n1 = (size_t)H1 * D_IN, n2 = (size_t)H2 * H1, n3 = (size_t)H3 * H2;
    split_w_kernel<<<(int)((n1 + 255) / 256), 256>>>(W1, W1s, W1s + n1, (int)n1);
    split_w_kernel<<<(int)((n2 + 255) / 256), 256>>>(W2, W2s, W2s + n2, (int)n2);
    split_w_kernel<<<(int)((n3 + 255) / 256), 256>>>(W3, W3s, W3s + n3, (int)n3);

    spikegen_kernel<<<(HALF_N + 255) / 256, 256>>>(images, S);

    const int nt1 = (M_TOT / 128) * (H1 / 128);   // 2560
    gemm_mma<<<(nt1 < pb ? nt1 : pb), 256, GEMM_SMEM>>>(
        S, W1s, W1s + n1, b1, cur1, H1, D_IN, nt1, H1 / 128);
    lif_kernel<<<(B_SZ * H1 + 255) / 256, 256>>>(cur1, s1, B_SZ * H1);

    const int nt2 = (M_TOT / 128) * (H2 / 128);   // 1280
    gemm_mma<<<(nt2 < pb ? nt2 : pb), 256, GEMM_SMEM>>>(
        s1, W2s, W2s + n2, b2, cur2, H2, H1, nt2, H2 / 128);
    lif_kernel<<<(B_SZ * H2 + 255) / 256, 256>>>(cur2, s2, B_SZ * H2);

    const int nt3 = (M_TOT / 128) * (H3 / 128);   // 640
    gemm_mma<<<(nt3 < pb ? nt3 : pb), 256, GEMM_SMEM>>>(
        s2, W3s, W3s + n3, b3, cur3, H3, H2, nt3, H3 / 128);
    lif_sum_kernel<<<(B_SZ * H3 + 255) / 256, 256>>>(cur3, s3sum, B_SZ * H3);

    head_kernel<<<(B_SZ + 255) / 256, 256>>>(s3sum, W4, b4, out);
}

// round 12
// speedup vs baseline: 1.0814x; 1.0696x over previous
#include <cuda_runtime.h>
#include <cuda_fp16.h>
#include <cstdint>

// ---------------- problem constants ----------------
#define T_STEPS 10
#define B_SZ    8192
#define D_IN    1024
#define H1      512
#define H2      256
#define H3      128
#define N_OUT   10
#define M_TOT   (T_STEPS * B_SZ)                          // 81920
#define HALF_N  ((uint32_t)(T_STEPS * B_SZ * D_IN / 2))   // 41,943,040

// b-major rows: m = b*10 + t
__device__ __half g_S   [(size_t)M_TOT * D_IN];           // 167 MB fp16 spikes
__device__ float  g_cur1[(size_t)M_TOT * H1];             // boundary rows only
__device__ __half g_s1  [(size_t)M_TOT * H1];
__device__ float  g_cur2[(size_t)M_TOT * H2];
__device__ __half g_s2  [(size_t)M_TOT * H2];
__device__ float  g_cur3[(size_t)M_TOT * H3];
__device__ float  g_s3sum[(size_t)B_SZ * H3];
__device__ __half g_W1s[2][(size_t)H1 * D_IN];
__device__ __half g_W2s[2][(size_t)H2 * H1];
__device__ __half g_W3s[2][(size_t)H3 * H2];

// ---------------- PTX helpers ----------------
__device__ __forceinline__ uint32_t smem_u32(const void* p) {
    uint32_t a;
    asm("{ .reg .u64 t; cvta.to.shared.u64 t, %1; cvt.u32.u64 %0, t; }" : "=r"(a) : "l"(p));
    return a;
}
__device__ __forceinline__ void cp16(uint32_t dst, const void* src) {
    asm volatile("cp.async.cg.shared.global [%0], [%1], 16;" :: "r"(dst), "l"(src) : "memory");
}
__device__ __forceinline__ void cp_commit() { asm volatile("cp.async.commit_group;" ::: "memory"); }
template<int N> __device__ __forceinline__ void cp_wait() {
    asm volatile("cp.async.wait_group %0;" :: "n"(N) : "memory");
}
__device__ __forceinline__ void ldsm4(uint32_t* r, uint32_t addr) {
    asm volatile("ldmatrix.sync.aligned.m8n8.x4.shared.b16 {%0,%1,%2,%3}, [%4];"
                 : "=r"(r[0]), "=r"(r[1]), "=r"(r[2]), "=r"(r[3]) : "r"(addr));
}
__device__ __forceinline__ void mma16816(float* d, const uint32_t* a, const uint32_t* b) {
    asm volatile(
        "mma.sync.aligned.m16n8k16.row.col.f32.f16.f16.f32 "
        "{%0,%1,%2,%3}, {%4,%5,%6,%7}, {%8,%9}, {%0,%1,%2,%3};"
        : "+f"(d[0]), "+f"(d[1]), "+f"(d[2]), "+f"(d[3])
        : "r"(a[0]), "r"(a[1]), "r"(a[2]), "r"(a[3]), "r"(b[0]), "r"(b[1]));
}

// ---------------- Threefry-2x32-20, key = (0, 42) ----------------
__device__ __forceinline__ uint32_t rotl32(uint32_t v, int r) {
    return (v << r) | (v >> (32 - r));
}
__device__ __forceinline__ void threefry_0_42(uint32_t x0, uint32_t x1,
                                              uint32_t& y0, uint32_t& y1) {
    const uint32_t k0 = 0u, k1 = 42u;
    const uint32_t k2 = k0 ^ k1 ^ 0x1BD11BDAu;
    x0 += k0; x1 += k1;
#define TF_RND(r) { x0 += x1; x1 = rotl32(x1, r); x1 ^= x0; }
    TF_RND(13) TF_RND(15) TF_RND(26) TF_RND(6)
    x0 += k1; x1 += k2 + 1u;
    TF_RND(17) TF_RND(29) TF_RND(16) TF_RND(24)
    x0 += k2; x1 += k0 + 2u;
    TF_RND(13) TF_RND(15) TF_RND(26) TF_RND(6)
    x0 += k0; x1 += k1 + 3u;
    TF_RND(17) TF_RND(29) TF_RND(16) TF_RND(24)
    x0 += k1; x1 += k2 + 4u;
    TF_RND(13) TF_RND(15) TF_RND(26) TF_RND(6)
    x0 += k2; x1 += k0 + 5u;
#undef TF_RND
    y0 = x0; y1 = x1;
}
__device__ __forceinline__ float bits_to_unit(uint32_t bits) {
    return __uint_as_float((bits >> 9) | 0x3f800000u) - 1.0f;
}

// b-major spike store: row = b*10 + t. Counter pair (i, i+HALF) = (t, t+5)
// of the SAME (b, d).
__global__ void spikegen_kernel(const float* __restrict__ images, __half* __restrict__ S) {
    uint32_t i = blockIdx.x * 256u + threadIdx.x;
    if (i >= HALF_N) return;
    uint32_t y0, y1;
    threefry_0_42(i, i + HALF_N, y0, y1);
    uint32_t t = i >> 23;                    // B*D = 2^23
    uint32_t r = i & 0x7FFFFFu;
    float img = images[r];
    uint32_t b = r >> 10;
    uint32_t d = r & 1023u;
    size_t base = ((size_t)(b * 10u) << 10) + d;
    S[base + ((size_t)t << 10)]       = __float2half((bits_to_unit(y0) < img) ? 1.0f : 0.0f);
    S[base + ((size_t)(t + 5) << 10)] = __float2half((bits_to_unit(y1) < img) ? 1.0f : 0.0f);
}

// ---------------- weight 2-way fp16 split (scaled residual) ----------------
__global__ void split_w_kernel(const float* __restrict__ W, __half* __restrict__ a,
                               __half* __restrict__ b, int n) {
    int i = blockIdx.x * 256 + threadIdx.x;
    if (i >= n) return;
    float w = W[i];
    __half h = __float2half(w);
    float r = w - __half2float(h);
    a[i] = h;
    b[i] = __float2half(r * 2048.0f);
}

// ---------------- mma.sync GEMM + fused LIF epilogue ----------------
// R9 core: BM=128, BN=128, BK=64, 2 stages, 1 barrier/chunk, 256 threads
// (8 warps 2x4), warp tile m64 x n32, static grid.
// Epilogue: stage 128x128 fp32 in pipeline smem; LIF complete batches in-tile
// (b-major: 12-13 per tile); boundary rows spill fp32 cur for fixup kernel.
#define ROWB 144
#define A_SZ   (128 * ROWB)                 // 18432 B
#define W_SZ   (128 * ROWB)                 // 18432 B
#define STAGE_SZ (A_SZ + 2 * W_SZ)          // 55296 B
#define GEMM_SMEM (2 * STAGE_SZ)            // 110592 B
#define EPS 130                             // epilogue smem stride (floats)

__device__ __forceinline__ void load_chunk(
    const __half* __restrict__ A, const __half* __restrict__ Wa,
    const __half* __restrict__ Wb, uint32_t sbase, int stage,
    int m0, int n0, int K, int c, int tid)
{
    uint32_t st = sbase + stage * STAGE_SZ;
    const int k0 = c * 64;
    const __half* Ab = A + (size_t)m0 * K + k0;
#pragma unroll
    for (int i = 0; i < 4; i++) {
        int idx = i * 256 + tid;
        int row = idx >> 3, q = idx & 7;
        cp16(st + (uint32_t)(row * ROWB + q * 16), Ab + (size_t)row * K + q * 8);
    }
    const __half* const Ws[2] = {Wa, Wb};
#pragma unroll
    for (int s = 0; s < 2; s++) {
        const __half* Wp = Ws[s] + (size_t)n0 * K + k0;
        uint32_t bs = st + A_SZ + s * W_SZ;
#pragma unroll
        for (int i = 0; i < 4; i++) {
            int idx = i * 256 + tid;
            int row = idx >> 3, q = idx & 7;
            cp16(bs + (uint32_t)(row * ROWB + q * 16), Wp + (size_t)row * K + q * 8);
        }
    }
    cp_commit();
}

template<int MODE>  // 0: LIF -> fp16 spikes; 1: LIF -> float spike sum
__global__ __launch_bounds__(256, 2)
void gemm_lif(const __half* __restrict__ A,
              const __half* __restrict__ Wa,
              const __half* __restrict__ Wb,
              const float* __restrict__ bias,
              __half* __restrict__ Sout,
              float* __restrict__ SumOut,
              float* __restrict__ Cur,
              int N, int K)
{
    extern __shared__ char smem[];
    const uint32_t sbase = smem_u32(smem);
    const int tid  = threadIdx.x;
    const int warp = tid >> 5;
    const int lane = tid & 31;
    const int wm = warp >> 2;                 // m offset wm*64
    const int wn = warp & 3;                  // n offset wn*32
    const int m0 = blockIdx.y * 128;
    const int n0 = blockIdx.x * 128;
    const int NC = K >> 6;

    float acc[4][4][4];
#pragma unroll
    for (int mt = 0; mt < 4; mt++)
#pragma unroll
        for (int nt = 0; nt < 4; nt++)
#pragma unroll
            for (int r = 0; r < 4; r++) acc[mt][nt][r] = 0.0f;

    load_chunk(A, Wa, Wb, sbase, 0, m0, n0, K, 0, tid);

    const uint32_t a_row = (uint32_t)(lane & 15) * ROWB;
    const uint32_t a_col = (uint32_t)(lane >> 4) * 16;
    const uint32_t b_row = (uint32_t)((lane & 7) + ((lane >> 4) & 1) * 8) * ROWB;
    const uint32_t b_col = (uint32_t)((lane >> 3) & 1) * 16;
    const __half2 sc2 = __half2half2(__ushort_as_half((unsigned short)0x1000)); // 2^-11

    for (int c = 0; c < NC; c++) {
        cp_wait<0>();
        __syncthreads();
        if (c + 1 < NC)
            load_chunk(A, Wa, Wb, sbase, (c + 1) & 1, m0, n0, K, c + 1, tid);

        uint32_t st = sbase + (c & 1) * STAGE_SZ;
#pragma unroll
        for (int ks = 0; ks < 4; ks++) {
            uint32_t a[4][4];
#pragma unroll
            for (int mt = 0; mt < 4; mt++) {
                uint32_t addr = st + (uint32_t)(wm * 64 + mt * 16) * ROWB + a_row
                              + (uint32_t)ks * 32 + a_col;
                ldsm4(a[mt], addr);
            }
            // ---- term 0: A @ Wa ----
            {
                uint32_t bfr[4][2];
#pragma unroll
                for (int p = 0; p < 2; p++) {
                    uint32_t addr = st + A_SZ
                                  + (uint32_t)(wn * 32 + p * 16) * ROWB + b_row
                                  + (uint32_t)ks * 32 + b_col;
                    uint32_t r[4];
                    ldsm4(r, addr);
                    bfr[p * 2 + 0][0] = r[0]; bfr[p * 2 + 0][1] = r[1];
                    bfr[p * 2 + 1][0] = r[2]; bfr[p * 2 + 1][1] = r[3];
                }
#pragma unroll
                for (int mt = 0; mt < 4; mt++)
#pragma unroll
                    for (int nt = 0; nt < 4; nt++)
                        mma16816(acc[mt][nt], a[mt], bfr[nt]);
            }
            // scale A fragment: spikes 1 -> 2^-11 (exact)
#pragma unroll
            for (int mt = 0; mt < 4; mt++)
#pragma unroll
                for (int j = 0; j < 4; j++) {
                    __half2 v = *(__half2*)&a[mt][j];
                    v = __hmul2(v, sc2);
                    a[mt][j] = *(uint32_t*)&v;
                }
            // ---- term 1: (2^-11 * A) @ Wb ----
            {
                uint32_t bfr[4][2];
#pragma unroll
                for (int p = 0; p < 2; p++) {
                    uint32_t addr = st + A_SZ + W_SZ
                                  + (uint32_t)(wn * 32 + p * 16) * ROWB + b_row
                                  + (uint32_t)ks * 32 + b_col;
                    uint32_t r[4];
                    ldsm4(r, addr);
                    bfr[p * 2 + 0][0] = r[0]; bfr[p * 2 + 0][1] = r[1];
                    bfr[p * 2 + 1][0] = r[2]; bfr[p * 2 + 1][1] = r[3];
                }
#pragma unroll
                for (int mt = 0; mt < 4; mt++)
#pragma unroll
                    for (int nt = 0; nt < 4; nt++)
                        mma16816(acc[mt][nt], a[mt], bfr[nt]);
            }
        }
    }

    // ---- epilogue: stage tile in smem, LIF interior batches, spill boundary ----
    __syncthreads();
    float* ep = (float*)smem;                 // 128 x EPS floats = 66560 B
#pragma unroll
    for (int nt = 0; nt < 4; nt++) {
        const int col = wn * 32 + nt * 8 + (lane & 3) * 2;
#pragma unroll
        for (int mt = 0; mt < 4; mt++) {
            const int r0 = wm * 64 + mt * 16 + (lane >> 2);
            *(float2*)&ep[(size_t)r0 * EPS + col] =
                make_float2(acc[mt][nt][0], acc[mt][nt][1]);
            *(float2*)&ep[(size_t)(r0 + 8) * EPS + col] =
                make_float2(acc[mt][nt][2], acc[mt][nt][3]);
        }
    }
    __syncthreads();

    // interior batches fully inside [m0, m0+128): kb0..kb1
    const int kb0 = (m0 + 9) / 10;
    const int kb1 = (m0 + 118) / 10;
    const int nint = (kb1 - kb0 + 1) * 128;
    for (int idx = tid; idx < nint; idx += 256) {
        const int k   = kb0 + (idx >> 7);
        const int col = idx & 127;
        const float bz = bias[n0 + col];
        float mem = 0.0f;
        float s = 0.0f;
#pragma unroll
        for (int t = 0; t < T_STEPS; t++) {
            const int lr = k * 10 + t - m0;
            float cur = __fadd_rn(ep[(size_t)lr * EPS + col], bz);
            float rst = (mem > 1.0f) ? 1.0f : 0.0f;
            mem = __fmul_rn(0.9f, mem);
            mem = __fadd_rn(mem, cur);
            mem = __fsub_rn(mem, rst);
            bool spk = (__fsub_rn(mem, 1.0f) > 0.0f);
            if (MODE == 0) {
                Sout[((size_t)k * 10 + t) * N + (n0 + col)] =
                    __float2half(spk ? 1.0f : 0.0f);
            } else {
                if (spk) s += 1.0f;
            }
        }
        if (MODE == 1) SumOut[(size_t)k * 128 + col] = s;
    }

    // boundary rows (split batches): spill cur (+bias) for fixup kernel
    const int nb_lo = kb0 * 10 - m0;                 // rows [0, nb_lo)
    const int nb_hi = m0 + 128 - (kb1 + 1) * 10;     // rows [128-nb_hi, 128)
    const int nbr = (nb_lo + nb_hi) * 128;
    for (int idx = tid; idx < nbr; idx += 256) {
        const int j   = idx >> 7;
        const int col = idx & 127;
        const int r   = (j < nb_lo) ? j : (128 - nb_hi + (j - nb_lo));
        Cur[(size_t)(m0 + r) * N + (n0 + col)] = ep[(size_t)r * EPS + col] + bias[n0 + col];
    }
}

// ---------------- fixup: LIF for batches split across tile boundaries ----------
template<int MODE>
__global__ void fixup_lif(const float* __restrict__ Cur, __half* __restrict__ Sout,
                          float* __restrict__ SumOut, int N) {
    int idx = blockIdx.x * 256 + threadIdx.x;
    if (idx >= B_SZ * N) return;
    int k = idx / N;
    int col = idx - k * N;
    if ((k * 10) / 128 == (k * 10 + 9) / 128) return;   // not split
    float mem = 0.0f, s = 0.0f;
#pragma unroll
    for (int t = 0; t < T_STEPS; t++) {
        float cur = Cur[((size_t)k * 10 + t) * N + col];
        float rst = (mem > 1.0f) ? 1.0f : 0.0f;
        mem = __fmul_rn(0.9f, mem);
        mem = __fadd_rn(mem, cur);
        mem = __fsub_rn(mem, rst);
        bool spk = (__fsub_rn(mem, 1.0f) > 0.0f);
        if (MODE == 0) {
            Sout[((size_t)k * 10 + t) * N + col] = __float2half(spk ? 1.0f : 0.0f);
        } else {
            if (spk) s += 1.0f;
        }
    }
    if (MODE == 1) SumOut[(size_t)k * 128 + col] = s;
}

// ---------------- head: Z = S3sum @ W4^T + 10*b4, softmax ----------------
__global__ void head_kernel(const float* __restrict__ S3sum, const float* __restrict__ W4,
                            const float* __restrict__ b4, float* __restrict__ out) {
    int b = blockIdx.x * 256 + threadIdx.x;
    if (b >= B_SZ) return;
    float acc[N_OUT];
#pragma unroll
    for (int c = 0; c < N_OUT; c++) acc[c] = 10.0f * b4[c];
    const float* row = S3sum + (size_t)b * H3;
#pragma unroll 4
    for (int j = 0; j < H3; j++) {
        float x = row[j];
        if (x != 0.0f) {
#pragma unroll
            for (int c = 0; c < N_OUT; c++) acc[c] += x * __ldg(&W4[c * H3 + j]);
        }
    }
    float m = acc[0];
#pragma unroll
    for (int c = 1; c < N_OUT; c++) m = fmaxf(m, acc[c]);
    float sum = 0.0f, e[N_OUT];
#pragma unroll
    for (int c = 0; c < N_OUT; c++) { e[c] = expf(acc[c] - m); sum += e[c]; }
    float inv = 1.0f / sum;
#pragma unroll
    for (int c = 0; c < N_OUT; c++) out[(size_t)b * N_OUT + c] = e[c] * inv;
}

// ---------------- launch ----------------
extern "C" void kernel_launch(void* const* d_in, const int* in_sizes, int n_in,
                              void* d_out, int out_size) {
    const float* images = (const float*)d_in[0];
    const float* W1 = (const float*)d_in[1];
    const float* b1 = (const float*)d_in[2];
    const float* W2 = (const float*)d_in[3];
    const float* b2 = (const float*)d_in[4];
    const float* W3 = (const float*)d_in[5];
    const float* b3 = (const float*)d_in[6];
    const float* W4 = (const float*)d_in[7];
    const float* b4 = (const float*)d_in[8];
    float* out = (float*)d_out;

    __half *S, *s1, *s2, *W1s, *W2s, *W3s;
    float *cur1, *cur2, *cur3, *s3sum;
    cudaGetSymbolAddress((void**)&S,     g_S);
    cudaGetSymbolAddress((void**)&cur1,  g_cur1);
    cudaGetSymbolAddress((void**)&s1,    g_s1);
    cudaGetSymbolAddress((void**)&cur2,  g_cur2);
    cudaGetSymbolAddress((void**)&s2,    g_s2);
    cudaGetSymbolAddress((void**)&cur3,  g_cur3);
    cudaGetSymbolAddress((void**)&s3sum, g_s3sum);
    cudaGetSymbolAddress((void**)&W1s,   g_W1s);
    cudaGetSymbolAddress((void**)&W2s,   g_W2s);
    cudaGetSymbolAddress((void**)&W3s,   g_W3s);

    cudaFuncSetAttribute(gemm_lif<0>, cudaFuncAttributeMaxDynamicSharedMemorySize, GEMM_SMEM);
    cudaFuncSetAttribute(gemm_lif<1>, cudaFuncAttributeMaxDynamicSharedMemorySize, GEMM_SMEM);

    const size_t n1 = (size_t)H1 * D_IN, n2 = (size_t)H2 * H1, n3 = (size_t)H3 * H2;
    split_w_kernel<<<(int)((n1 + 255) / 256), 256>>>(W1, W1s, W1s + n1, (int)n1);
    split_w_kernel<<<(int)((n2 + 255) / 256), 256>>>(W2, W2s, W2s + n2, (int)n2);
    split_w_kernel<<<(int)((n3 + 255) / 256), 256>>>(W3, W3s, W3s + n3, (int)n3);

    spikegen_kernel<<<(HALF_N + 255) / 256, 256>>>(images, S);

    gemm_lif<0><<<dim3(H1 / 128, M_TOT / 128), 256, GEMM_SMEM>>>(
        S, W1s, W1s + n1, b1, s1, nullptr, cur1, H1, D_IN);
    fixup_lif<0><<<(B_SZ * H1 + 255) / 256, 256>>>(cur1, s1, nullptr, H1);

    gemm_lif<0><<<dim3(H2 / 128, M_TOT / 128), 256, GEMM_SMEM>>>(
        s1, W2s, W2s + n2, b2, s2, nullptr, cur2, H2, H1);
    fixup_lif<0><<<(B_SZ * H2 + 255) / 256, 256>>>(cur2, s2, nullptr, H2);

    gemm_lif<1><<<dim3(H3 / 128, M_TOT / 128), 256, GEMM_SMEM>>>(
        s2, W3s, W3s + n3, b3, nullptr, s3sum, cur3, H3, H2);
    fixup_lif<1><<<(B_SZ * H3 + 255) / 256, 256>>>(cur3, nullptr, s3sum, H3);

    head_kernel<<<(B_SZ + 255) / 256, 256>>>(s3sum, W4, b4, out);
}

// round 13
// speedup vs baseline: 1.1182x; 1.0341x over previous
#include <cuda_runtime.h>
#include <cuda_fp16.h>
#include <cstdint>

// ---------------- problem constants ----------------
#define T_STEPS 10
#define B_SZ    8192
#define D_IN    1024
#define H1      512
#define H2      256
#define H3      128
#define N_OUT   10
#define M_TOT   (T_STEPS * B_SZ)                          // 81920
#define HALF_N  ((uint32_t)(T_STEPS * B_SZ * D_IN / 2))   // 41,943,040

// b-major rows: m = b*10 + t
__device__ __half g_S   [(size_t)M_TOT * D_IN];           // 167 MB fp16 spikes
__device__ float  g_cur1[(size_t)M_TOT * H1];             // boundary rows only
__device__ __half g_s1  [(size_t)M_TOT * H1];
__device__ float  g_cur2[(size_t)M_TOT * H2];
__device__ __half g_s2  [(size_t)M_TOT * H2];
__device__ float  g_cur3[(size_t)M_TOT * H3];
__device__ float  g_s3sum[(size_t)B_SZ * H3];
__device__ __half g_W1s[2][(size_t)H1 * D_IN];
__device__ __half g_W2s[2][(size_t)H2 * H1];
__device__ __half g_W3s[2][(size_t)H3 * H2];

// ---------------- PTX helpers ----------------
__device__ __forceinline__ uint32_t smem_u32(const void* p) {
    uint32_t a;
    asm("{ .reg .u64 t; cvta.to.shared.u64 t, %1; cvt.u32.u64 %0, t; }" : "=r"(a) : "l"(p));
    return a;
}
__device__ __forceinline__ void cp16(uint32_t dst, const void* src) {
    asm volatile("cp.async.cg.shared.global [%0], [%1], 16;" :: "r"(dst), "l"(src) : "memory");
}
__device__ __forceinline__ void cp_commit() { asm volatile("cp.async.commit_group;" ::: "memory"); }
template<int N> __device__ __forceinline__ void cp_wait() {
    asm volatile("cp.async.wait_group %0;" :: "n"(N) : "memory");
}
__device__ __forceinline__ void ldsm4(uint32_t* r, uint32_t addr) {
    asm volatile("ldmatrix.sync.aligned.m8n8.x4.shared.b16 {%0,%1,%2,%3}, [%4];"
                 : "=r"(r[0]), "=r"(r[1]), "=r"(r[2]), "=r"(r[3]) : "r"(addr));
}
__device__ __forceinline__ void mma16816(float* d, const uint32_t* a, const uint32_t* b) {
    asm volatile(
        "mma.sync.aligned.m16n8k16.row.col.f32.f16.f16.f32 "
        "{%0,%1,%2,%3}, {%4,%5,%6,%7}, {%8,%9}, {%0,%1,%2,%3};"
        : "+f"(d[0]), "+f"(d[1]), "+f"(d[2]), "+f"(d[3])
        : "r"(a[0]), "r"(a[1]), "r"(a[2]), "r"(a[3]), "r"(b[0]), "r"(b[1]));
}

// ---------------- Threefry-2x32-20, key = (0, 42) ----------------
__device__ __forceinline__ uint32_t rotl32(uint32_t v, int r) {
    return (v << r) | (v >> (32 - r));
}
__device__ __forceinline__ void threefry_0_42(uint32_t x0, uint32_t x1,
                                              uint32_t& y0, uint32_t& y1) {
    const uint32_t k0 = 0u, k1 = 42u;
    const uint32_t k2 = k0 ^ k1 ^ 0x1BD11BDAu;
    x0 += k0; x1 += k1;
#define TF_RND(r) { x0 += x1; x1 = rotl32(x1, r); x1 ^= x0; }
    TF_RND(13) TF_RND(15) TF_RND(26) TF_RND(6)
    x0 += k1; x1 += k2 + 1u;
    TF_RND(17) TF_RND(29) TF_RND(16) TF_RND(24)
    x0 += k2; x1 += k0 + 2u;
    TF_RND(13) TF_RND(15) TF_RND(26) TF_RND(6)
    x0 += k0; x1 += k1 + 3u;
    TF_RND(17) TF_RND(29) TF_RND(16) TF_RND(24)
    x0 += k1; x1 += k2 + 4u;
    TF_RND(13) TF_RND(15) TF_RND(26) TF_RND(6)
    x0 += k2; x1 += k0 + 5u;
#undef TF_RND
    y0 = x0; y1 = x1;
}
__device__ __forceinline__ float bits_to_unit(uint32_t bits) {
    return __uint_as_float((bits >> 9) | 0x3f800000u) - 1.0f;
}
__device__ __forceinline__ __half spike_of(uint32_t bits, float img) {
    return __ushort_as_half((bits_to_unit(bits) < img) ? (unsigned short)0x3C00
                                                       : (unsigned short)0);
}

// b-major spike store: row = b*10 + t. Each thread handles TWO adjacent
// counters (i, i+1): same (t, b), columns d and d+1 -> index math amortized,
// 4 outputs as two __half2 stores. (i even => d even => no row crossing.)
__global__ void spikegen_kernel(const float* __restrict__ images, __half* __restrict__ S) {
    uint32_t j = blockIdx.x * 256u + threadIdx.x;
    uint32_t i = j * 2u;
    if (i >= HALF_N) return;
    uint32_t y0a, y1a, y0b, y1b;
    threefry_0_42(i,      i + HALF_N,      y0a, y1a);
    threefry_0_42(i + 1u, i + 1u + HALF_N, y0b, y1b);
    uint32_t t = i >> 23;                    // B*D = 2^23
    uint32_t r = i & 0x7FFFFFu;
    float img0 = images[r];
    float img1 = images[r + 1u];
    uint32_t b = r >> 10;
    uint32_t d = r & 1023u;
    size_t base = ((size_t)(b * 10u) << 10) + d;
    __half2 lo = __halves2half2(spike_of(y0a, img0), spike_of(y0b, img1));
    __half2 hi = __halves2half2(spike_of(y1a, img0), spike_of(y1b, img1));
    *(__half2*)(S + base + ((size_t)t << 10))        = lo;
    *(__half2*)(S + base + ((size_t)(t + 5u) << 10)) = hi;
}

// ---------------- weight 2-way fp16 split (one kernel for all layers) --------
__global__ void split_w_all(const float* __restrict__ W1, const float* __restrict__ W2,
                            const float* __restrict__ W3,
                            __half* __restrict__ W1s, __half* __restrict__ W2s,
                            __half* __restrict__ W3s) {
    const int n1 = H1 * D_IN, n2 = H2 * H1, n3 = H3 * H2;
    int i = blockIdx.x * 256 + threadIdx.x;
    const float* W; __half *a, *b; int k;
    if (i < n1)                { W = W1; a = W1s; b = W1s + n1; k = i; }
    else if (i < n1 + n2)      { W = W2; a = W2s; b = W2s + n2; k = i - n1; }
    else if (i < n1 + n2 + n3) { W = W3; a = W3s; b = W3s + n3; k = i - n1 - n2; }
    else return;
    float w = W[k];
    __half h = __float2half(w);
    float r = w - __half2float(h);
    a[k] = h;
    b[k] = __float2half(r * 2048.0f);
}

// ---------------- mma.sync GEMM + fused LIF epilogue (R12, unchanged) --------
#define ROWB 144
#define A_SZ   (128 * ROWB)                 // 18432 B
#define W_SZ   (128 * ROWB)                 // 18432 B
#define STAGE_SZ (A_SZ + 2 * W_SZ)          // 55296 B
#define GEMM_SMEM (2 * STAGE_SZ)            // 110592 B
#define EPS 130                             // epilogue smem stride (floats)

__device__ __forceinline__ void load_chunk(
    const __half* __restrict__ A, const __half* __restrict__ Wa,
    const __half* __restrict__ Wb, uint32_t sbase, int stage,
    int m0, int n0, int K, int c, int tid)
{
    uint32_t st = sbase + stage * STAGE_SZ;
    const int k0 = c * 64;
    const __half* Ab = A + (size_t)m0 * K + k0;
#pragma unroll
    for (int i = 0; i < 4; i++) {
        int idx = i * 256 + tid;
        int row = idx >> 3, q = idx & 7;
        cp16(st + (uint32_t)(row * ROWB + q * 16), Ab + (size_t)row * K + q * 8);
    }
    const __half* const Ws[2] = {Wa, Wb};
#pragma unroll
    for (int s = 0; s < 2; s++) {
        const __half* Wp = Ws[s] + (size_t)n0 * K + k0;
        uint32_t bs = st + A_SZ + s * W_SZ;
#pragma unroll
        for (int i = 0; i < 4; i++) {
            int idx = i * 256 + tid;
            int row = idx >> 3, q = idx & 7;
            cp16(bs + (uint32_t)(row * ROWB + q * 16), Wp + (size_t)row * K + q * 8);
        }
    }
    cp_commit();
}

template<int MODE>  // 0: LIF -> fp16 spikes; 1: LIF -> float spike sum
__global__ __launch_bounds__(256, 2)
void gemm_lif(const __half* __restrict__ A,
              const __half* __restrict__ Wa,
              const __half* __restrict__ Wb,
              const float* __restrict__ bias,
              __half* __restrict__ Sout,
              float* __restrict__ SumOut,
              float* __restrict__ Cur,
              int N, int K)
{
    extern __shared__ char smem[];
    const uint32_t sbase = smem_u32(smem);
    const int tid  = threadIdx.x;
    const int warp = tid >> 5;
    const int lane = tid & 31;
    const int wm = warp >> 2;                 // m offset wm*64
    const int wn = warp & 3;                  // n offset wn*32
    const int m0 = blockIdx.y * 128;
    const int n0 = blockIdx.x * 128;
    const int NC = K >> 6;

    float acc[4][4][4];
#pragma unroll
    for (int mt = 0; mt < 4; mt++)
#pragma unroll
        for (int nt = 0; nt < 4; nt++)
#pragma unroll
            for (int r = 0; r < 4; r++) acc[mt][nt][r] = 0.0f;

    load_chunk(A, Wa, Wb, sbase, 0, m0, n0, K, 0, tid);

    const uint32_t a_row = (uint32_t)(lane & 15) * ROWB;
    const uint32_t a_col = (uint32_t)(lane >> 4) * 16;
    const uint32_t b_row = (uint32_t)((lane & 7) + ((lane >> 4) & 1) * 8) * ROWB;
    const uint32_t b_col = (uint32_t)((lane >> 3) & 1) * 16;
    const __half2 sc2 = __half2half2(__ushort_as_half((unsigned short)0x1000)); // 2^-11

    for (int c = 0; c < NC; c++) {
        cp_wait<0>();
        __syncthreads();
        if (c + 1 < NC)
            load_chunk(A, Wa, Wb, sbase, (c + 1) & 1, m0, n0, K, c + 1, tid);

        uint32_t st = sbase + (c & 1) * STAGE_SZ;
#pragma unroll
        for (int ks = 0; ks < 4; ks++) {
            uint32_t a[4][4];
#pragma unroll
            for (int mt = 0; mt < 4; mt++) {
                uint32_t addr = st + (uint32_t)(wm * 64 + mt * 16) * ROWB + a_row
                              + (uint32_t)ks * 32 + a_col;
                ldsm4(a[mt], addr);
            }
            // ---- term 0: A @ Wa ----
            {
                uint32_t bfr[4][2];
#pragma unroll
                for (int p = 0; p < 2; p++) {
                    uint32_t addr = st + A_SZ
                                  + (uint32_t)(wn * 32 + p * 16) * ROWB + b_row
                                  + (uint32_t)ks * 32 + b_col;
                    uint32_t r[4];
                    ldsm4(r, addr);
                    bfr[p * 2 + 0][0] = r[0]; bfr[p * 2 + 0][1] = r[1];
                    bfr[p * 2 + 1][0] = r[2]; bfr[p * 2 + 1][1] = r[3];
                }
#pragma unroll
                for (int mt = 0; mt < 4; mt++)
#pragma unroll
                    for (int nt = 0; nt < 4; nt++)
                        mma16816(acc[mt][nt], a[mt], bfr[nt]);
            }
            // scale A fragment: spikes 1 -> 2^-11 (exact)
#pragma unroll
            for (int mt = 0; mt < 4; mt++)
#pragma unroll
                for (int j = 0; j < 4; j++) {
                    __half2 v = *(__half2*)&a[mt][j];
                    v = __hmul2(v, sc2);
                    a[mt][j] = *(uint32_t*)&v;
                }
            // ---- term 1: (2^-11 * A) @ Wb ----
            {
                uint32_t bfr[4][2];
#pragma unroll
                for (int p = 0; p < 2; p++) {
                    uint32_t addr = st + A_SZ + W_SZ
                                  + (uint32_t)(wn * 32 + p * 16) * ROWB + b_row
                                  + (uint32_t)ks * 32 + b_col;
                    uint32_t r[4];
                    ldsm4(r, addr);
                    bfr[p * 2 + 0][0] = r[0]; bfr[p * 2 + 0][1] = r[1];
                    bfr[p * 2 + 1][0] = r[2]; bfr[p * 2 + 1][1] = r[3];
                }
#pragma unroll
                for (int mt = 0; mt < 4; mt++)
#pragma unroll
                    for (int nt = 0; nt < 4; nt++)
                        mma16816(acc[mt][nt], a[mt], bfr[nt]);
            }
        }
    }

    // ---- epilogue: stage tile in smem, LIF interior batches, spill boundary ----
    __syncthreads();
    float* ep = (float*)smem;                 // 128 x EPS floats = 66560 B
#pragma unroll
    for (int nt = 0; nt < 4; nt++) {
        const int col = wn * 32 + nt * 8 + (lane & 3) * 2;
#pragma unroll
        for (int mt = 0; mt < 4; mt++) {
            const int r0 = wm * 64 + mt * 16 + (lane >> 2);
            *(float2*)&ep[(size_t)r0 * EPS + col] =
                make_float2(acc[mt][nt][0], acc[mt][nt][1]);
            *(float2*)&ep[(size_t)(r0 + 8) * EPS + col] =
                make_float2(acc[mt][nt][2], acc[mt][nt][3]);
        }
    }
    __syncthreads();

    const int kb0 = (m0 + 9) / 10;
    const int kb1 = (m0 + 118) / 10;
    const int nint = (kb1 - kb0 + 1) * 128;
    for (int idx = tid; idx < nint; idx += 256) {
        const int k   = kb0 + (idx >> 7);
        const int col = idx & 127;
        const float bz = bias[n0 + col];
        float mem = 0.0f;
        float s = 0.0f;
#pragma unroll
        for (int t = 0; t < T_STEPS; t++) {
            const int lr = k * 10 + t - m0;
            float cur = __fadd_rn(ep[(size_t)lr * EPS + col], bz);
            float rst = (mem > 1.0f) ? 1.0f : 0.0f;
            mem = __fmul_rn(0.9f, mem);
            mem = __fadd_rn(mem, cur);
            mem = __fsub_rn(mem, rst);
            bool spk = (__fsub_rn(mem, 1.0f) > 0.0f);
            if (MODE == 0) {
                Sout[((size_t)k * 10 + t) * N + (n0 + col)] =
                    __float2half(spk ? 1.0f : 0.0f);
            } else {
                if (spk) s += 1.0f;
            }
        }
        if (MODE == 1) SumOut[(size_t)k * 128 + col] = s;
    }

    const int nb_lo = kb0 * 10 - m0;
    const int nb_hi = m0 + 128 - (kb1 + 1) * 10;
    const int nbr = (nb_lo + nb_hi) * 128;
    for (int idx = tid; idx < nbr; idx += 256) {
        const int j   = idx >> 7;
        const int col = idx & 127;
        const int r   = (j < nb_lo) ? j : (128 - nb_hi + (j - nb_lo));
        Cur[(size_t)(m0 + r) * N + (n0 + col)] = ep[(size_t)r * EPS + col] + bias[n0 + col];
    }
}

// ---------------- fixup: LIF for the 512 split batches only ------------------
// split <=> k mod 64 in {12, 25, 38, 51}  (k = (j>>2)*64 + 12 + 13*(j&3))
#define N_SPLIT 512
template<int MODE>
__global__ void fixup_lif(const float* __restrict__ Cur, __half* __restrict__ Sout,
                          float* __restrict__ SumOut, int N) {
    int idx = blockIdx.x * 256 + threadIdx.x;
    if (idx >= N_SPLIT * N) return;
    int j = idx / N;
    int col = idx - j * N;
    int k = (j >> 2) * 64 + 12 + 13 * (j & 3);
    float mem = 0.0f, s = 0.0f;
#pragma unroll
    for (int t = 0; t < T_STEPS; t++) {
        float cur = Cur[((size_t)k * 10 + t) * N + col];
        float rst = (mem > 1.0f) ? 1.0f : 0.0f;
        mem = __fmul_rn(0.9f, mem);
        mem = __fadd_rn(mem, cur);
        mem = __fsub_rn(mem, rst);
        bool spk = (__fsub_rn(mem, 1.0f) > 0.0f);
        if (MODE == 0) {
            Sout[((size_t)k * 10 + t) * N + col] = __float2half(spk ? 1.0f : 0.0f);
        } else {
            if (spk) s += 1.0f;
        }
    }
    if (MODE == 1) SumOut[(size_t)k * 128 + col] = s;
}

// ---------------- head: Z = S3sum @ W4^T + 10*b4, softmax ----------------
__global__ void head_kernel(const float* __restrict__ S3sum, const float* __restrict__ W4,
                            const float* __restrict__ b4, float* __restrict__ out) {
    int b = blockIdx.x * 256 + threadIdx.x;
    if (b >= B_SZ) return;
    float acc[N_OUT];
#pragma unroll
    for (int c = 0; c < N_OUT; c++) acc[c] = 10.0f * b4[c];
    const float* row = S3sum + (size_t)b * H3;
#pragma unroll 4
    for (int j = 0; j < H3; j++) {
        float x = row[j];
        if (x != 0.0f) {
#pragma unroll
            for (int c = 0; c < N_OUT; c++) acc[c] += x * __ldg(&W4[c * H3 + j]);
        }
    }
    float m = acc[0];
#pragma unroll
    for (int c = 1; c < N_OUT; c++) m = fmaxf(m, acc[c]);
    float sum = 0.0f, e[N_OUT];
#pragma unroll
    for (int c = 0; c < N_OUT; c++) { e[c] = expf(acc[c] - m); sum += e[c]; }
    float inv = 1.0f / sum;
#pragma unroll
    for (int c = 0; c < N_OUT; c++) out[(size_t)b * N_OUT + c] = e[c] * inv;
}

// ---------------- launch ----------------
extern "C" void kernel_launch(void* const* d_in, const int* in_sizes, int n_in,
                              void* d_out, int out_size) {
    const float* images = (const float*)d_in[0];
    const float* W1 = (const float*)d_in[1];
    const float* b1 = (const float*)d_in[2];
    const float* W2 = (const float*)d_in[3];
    const float* b2 = (const float*)d_in[4];
    const float* W3 = (const float*)d_in[5];
    const float* b3 = (const float*)d_in[6];
    const float* W4 = (const float*)d_in[7];
    const float* b4 = (const float*)d_in[8];
    float* out = (float*)d_out;

    __half *S, *s1, *s2, *W1s, *W2s, *W3s;
    float *cur1, *cur2, *cur3, *s3sum;
    cudaGetSymbolAddress((void**)&S,     g_S);
    cudaGetSymbolAddress((void**)&cur1,  g_cur1);
    cudaGetSymbolAddress((void**)&s1,    g_s1);
    cudaGetSymbolAddress((void**)&cur2,  g_cur2);
    cudaGetSymbolAddress((void**)&s2,    g_s2);
    cudaGetSymbolAddress((void**)&cur3,  g_cur3);
    cudaGetSymbolAddress((void**)&s3sum, g_s3sum);
    cudaGetSymbolAddress((void**)&W1s,   g_W1s);
    cudaGetSymbolAddress((void**)&W2s,   g_W2s);
    cudaGetSymbolAddress((void**)&W3s,   g_W3s);

    cudaFuncSetAttribute(gemm_lif<0>, cudaFuncAttributeMaxDynamicSharedMemorySize, GEMM_SMEM);
    cudaFuncSetAttribute(gemm_lif<1>, cudaFuncAttributeMaxDynamicSharedMemorySize, GEMM_SMEM);

    const size_t n1 = (size_t)H1 * D_IN, n2 = (size_t)H2 * H1, n3 = (size_t)H3 * H2;
    const int nsplit_tot = (int)(n1 + n2 + n3);
    split_w_all<<<(nsplit_tot + 255) / 256, 256>>>(W1, W2, W3, W1s, W2s, W3s);

    spikegen_kernel<<<(HALF_N / 2 + 255) / 256, 256>>>(images, S);

    gemm_lif<0><<<dim3(H1 / 128, M_TOT / 128), 256, GEMM_SMEM>>>(
        S, W1s, W1s + n1, b1, s1, nullptr, cur1, H1, D_IN);
    fixup_lif<0><<<(N_SPLIT * H1 + 255) / 256, 256>>>(cur1, s1, nullptr, H1);

    gemm_lif<0><<<dim3(H2 / 128, M_TOT / 128), 256, GEMM_SMEM>>>(
        s1, W2s, W2s + n2, b2, s2, nullptr, cur2, H2, H1);
    fixup_lif<0><<<(N_SPLIT * H2 + 255) / 256, 256>>>(cur2, s2, nullptr, H2);

    gemm_lif<1><<<dim3(H3 / 128, M_TOT / 128), 256, GEMM_SMEM>>>(
        s2, W3s, W3s + n3, b3, nullptr, s3sum, cur3, H3, H2);
    fixup_lif<1><<<(N_SPLIT * H3 + 255) / 256, 256>>>(cur3, nullptr, s3sum, H3);

    head_kernel<<<(B_SZ + 255) / 256, 256>>>(s3sum, W4, b4, out);
}

// round 15
// speedup vs baseline: 1.1443x; 1.0233x over previous
#include <cuda_runtime.h>
#include <cuda_fp16.h>
#include <cstdint>

// ---------------- problem constants ----------------
#define T_STEPS 10
#define B_SZ    8192
#define D_IN    1024
#define H1      512
#define H2      256
#define H3      128
#define N_OUT   10
#define M_TOT   (T_STEPS * B_SZ)                          // 81920
#define HALF_N  ((uint32_t)(T_STEPS * B_SZ * D_IN / 2))   // 41,943,040

// b-major rows: m = b*10 + t
__device__ __half g_S   [(size_t)M_TOT * D_IN];           // 167 MB fp16 spikes
__device__ float  g_cur1[(size_t)M_TOT * H1];             // boundary rows only
__device__ __half g_s1  [(size_t)M_TOT * H1];
__device__ float  g_cur2[(size_t)M_TOT * H2];
__device__ __half g_s2  [(size_t)M_TOT * H2];
__device__ float  g_cur3[(size_t)M_TOT * H3];
__device__ float  g_s3sum[(size_t)B_SZ * H3];
__device__ __half g_W1s[2][(size_t)H1 * D_IN];
__device__ __half g_W2s[2][(size_t)H2 * H1];
__device__ __half g_W3s[2][(size_t)H3 * H2];

// ---------------- PTX helpers ----------------
__device__ __forceinline__ uint32_t smem_u32(const void* p) {
    uint32_t a;
    asm("{ .reg .u64 t; cvta.to.shared.u64 t, %1; cvt.u32.u64 %0, t; }" : "=r"(a) : "l"(p));
    return a;
}
__device__ __forceinline__ void cp16(uint32_t dst, const void* src) {
    asm volatile("cp.async.cg.shared.global [%0], [%1], 16;" :: "r"(dst), "l"(src) : "memory");
}
__device__ __forceinline__ void cp_commit() { asm volatile("cp.async.commit_group;" ::: "memory"); }
template<int N> __device__ __forceinline__ void cp_wait() {
    asm volatile("cp.async.wait_group %0;" :: "n"(N) : "memory");
}
__device__ __forceinline__ void ldsm4(uint32_t* r, uint32_t addr) {
    asm volatile("ldmatrix.sync.aligned.m8n8.x4.shared.b16 {%0,%1,%2,%3}, [%4];"
                 : "=r"(r[0]), "=r"(r[1]), "=r"(r[2]), "=r"(r[3]) : "r"(addr));
}
__device__ __forceinline__ void mma16816(float* d, const uint32_t* a, const uint32_t* b) {
    asm volatile(
        "mma.sync.aligned.m16n8k16.row.col.f32.f16.f16.f32 "
        "{%0,%1,%2,%3}, {%4,%5,%6,%7}, {%8,%9}, {%0,%1,%2,%3};"
        : "+f"(d[0]), "+f"(d[1]), "+f"(d[2]), "+f"(d[3])
        : "r"(a[0]), "r"(a[1]), "r"(a[2]), "r"(a[3]), "r"(b[0]), "r"(b[1]));
}

// ---------------- Threefry-2x32-20, key = (0, 42) ----------------
__device__ __forceinline__ uint32_t rotl32(uint32_t v, int r) {
    return (v << r) | (v >> (32 - r));
}
__device__ __forceinline__ void threefry_0_42(uint32_t x0, uint32_t x1,
                                              uint32_t& y0, uint32_t& y1) {
    const uint32_t k0 = 0u, k1 = 42u;
    const uint32_t k2 = k0 ^ k1 ^ 0x1BD11BDAu;
    x0 += k0; x1 += k1;
#define TF_RND(r) { x0 += x1; x1 = rotl32(x1, r); x1 ^= x0; }
    TF_RND(13) TF_RND(15) TF_RND(26) TF_RND(6)
    x0 += k1; x1 += k2 + 1u;
    TF_RND(17) TF_RND(29) TF_RND(16) TF_RND(24)
    x0 += k2; x1 += k0 + 2u;
    TF_RND(13) TF_RND(15) TF_RND(26) TF_RND(6)
    x0 += k0; x1 += k1 + 3u;
    TF_RND(17) TF_RND(29) TF_RND(16) TF_RND(24)
    x0 += k1; x1 += k2 + 4u;
    TF_RND(13) TF_RND(15) TF_RND(26) TF_RND(6)
    x0 += k2; x1 += k0 + 5u;
#undef TF_RND
    y0 = x0; y1 = x1;
}

// Exact integer spike test: u = (y>>9)*2^-23 < img  <=>  (y>>9) < ceil(img*2^23).
// img*2^23 is an exact exponent scale; cvt.ru gives the exact ceiling.
// Comparing the UNSHIFTED (y>>9) against ceil avoids any <<9 overflow for
// img arbitrarily close to 1 ((y>>9) <= 2^23-1 < 2^23 = max ceil).
__device__ __forceinline__ uint32_t thr_of(float img) {
    return __float2uint_ru(img * 8388608.0f);
}

// b-major spike store: row = b*10 + t. Each thread handles FOUR adjacent
// counters (i..i+3): same (t, b), columns d..d+3 -> index math amortized 4x,
// one float4 image load, outputs packed as two 8-byte stores per row.
__global__ void spikegen_kernel(const float* __restrict__ images, __half* __restrict__ S) {
    uint32_t j = blockIdx.x * 256u + threadIdx.x;
    uint32_t i = j * 4u;
    if (i >= HALF_N) return;
    uint32_t y0[4], y1[4];
#pragma unroll
    for (int q = 0; q < 4; q++)
        threefry_0_42(i + q, i + q + HALF_N, y0[q], y1[q]);
    uint32_t t = i >> 23;                    // B*D = 2^23
    uint32_t r = i & 0x7FFFFFu;              // multiple of 4
    float4 im = *(const float4*)(images + r);
    uint32_t th[4] = { thr_of(im.x), thr_of(im.y), thr_of(im.z), thr_of(im.w) };
    uint32_t b = r >> 10;
    uint32_t d = r & 1023u;
    size_t base = ((size_t)(b * 10u) << 10) + d;
    uint2 lo, hi;
    lo.x = ((y0[0] >> 9) < th[0] ? 0x3C00u : 0u) | ((y0[1] >> 9) < th[1] ? 0x3C000000u : 0u);
    lo.y = ((y0[2] >> 9) < th[2] ? 0x3C00u : 0u) | ((y0[3] >> 9) < th[3] ? 0x3C000000u : 0u);
    hi.x = ((y1[0] >> 9) < th[0] ? 0x3C00u : 0u) | ((y1[1] >> 9) < th[1] ? 0x3C000000u : 0u);
    hi.y = ((y1[2] >> 9) < th[2] ? 0x3C00u : 0u) | ((y1[3] >> 9) < th[3] ? 0x3C000000u : 0u);
    *(uint2*)(S + base + ((size_t)t << 10))        = lo;
    *(uint2*)(S + base + ((size_t)(t + 5u) << 10)) = hi;
}

// ---------------- weight 2-way fp16 split (one kernel for all layers) --------
__global__ void split_w_all(const float* __restrict__ W1, const float* __restrict__ W2,
                            const float* __restrict__ W3,
                            __half* __restrict__ W1s, __half* __restrict__ W2s,
                            __half* __restrict__ W3s) {
    const int n1 = H1 * D_IN, n2 = H2 * H1, n3 = H3 * H2;
    int i = blockIdx.x * 256 + threadIdx.x;
    const float* W; __half *a, *b; int k;
    if (i < n1)                { W = W1; a = W1s; b = W1s + n1; k = i; }
    else if (i < n1 + n2)      { W = W2; a = W2s; b = W2s + n2; k = i - n1; }
    else if (i < n1 + n2 + n3) { W = W3; a = W3s; b = W3s + n3; k = i - n1 - n2; }
    else return;
    float w = W[k];
    __half h = __float2half(w);
    float r = w - __half2float(h);
    a[k] = h;
    b[k] = __float2half(r * 2048.0f);
}

// ---------------- mma.sync GEMM + fused LIF epilogue --------
#define ROWB 144
#define A_SZ   (128 * ROWB)                 // 18432 B
#define W_SZ   (128 * ROWB)                 // 18432 B
#define STAGE_SZ (A_SZ + 2 * W_SZ)          // 55296 B
#define GEMM_SMEM (2 * STAGE_SZ)            // 110592 B
#define EPS 130                             // epilogue smem stride (floats)

__device__ __forceinline__ void load_chunk(
    const __half* __restrict__ A, const __half* __restrict__ Wa,
    const __half* __restrict__ Wb, uint32_t sbase, int stage,
    int m0, int n0, int K, int c, int tid)
{
    uint32_t st = sbase + stage * STAGE_SZ;
    const int k0 = c * 64;
    const __half* Ab = A + (size_t)m0 * K + k0;
#pragma unroll
    for (int i = 0; i < 4; i++) {
        int idx = i * 256 + tid;
        int row = idx >> 3, q = idx & 7;
        cp16(st + (uint32_t)(row * ROWB + q * 16), Ab + (size_t)row * K + q * 8);
    }
    const __half* const Ws[2] = {Wa, Wb};
#pragma unroll
    for (int s = 0; s < 2; s++) {
        const __half* Wp = Ws[s] + (size_t)n0 * K + k0;
        uint32_t bs = st + A_SZ + s * W_SZ;
#pragma unroll
        for (int i = 0; i < 4; i++) {
            int idx = i * 256 + tid;
            int row = idx >> 3, q = idx & 7;
            cp16(bs + (uint32_t)(row * ROWB + q * 16), Wp + (size_t)row * K + q * 8);
        }
    }
    cp_commit();
}

template<int MODE>  // 0: LIF -> fp16 spikes; 1: LIF -> float spike sum
__global__ __launch_bounds__(256, 2)
void gemm_lif(const __half* __restrict__ A,
              const __half* __restrict__ Wa,
              const __half* __restrict__ Wb,
              const float* __restrict__ bias,
              __half* __restrict__ Sout,
              float* __restrict__ SumOut,
              float* __restrict__ Cur,
              int N, int K)
{
    extern __shared__ char smem[];
    const uint32_t sbase = smem_u32(smem);
    const int tid  = threadIdx.x;
    const int warp = tid >> 5;
    const int lane = tid & 31;
    const int wm = warp >> 2;                 // m offset wm*64
    const int wn = warp & 3;                  // n offset wn*32
    const int m0 = blockIdx.y * 128;
    const int n0 = blockIdx.x * 128;
    const int NC = K >> 6;

    float acc[4][4][4];
#pragma unroll
    for (int mt = 0; mt < 4; mt++)
#pragma unroll
        for (int nt = 0; nt < 4; nt++)
#pragma unroll
            for (int r = 0; r < 4; r++) acc[mt][nt][r] = 0.0f;

    load_chunk(A, Wa, Wb, sbase, 0, m0, n0, K, 0, tid);

    const uint32_t a_row = (uint32_t)(lane & 15) * ROWB;
    const uint32_t a_col = (uint32_t)(lane >> 4) * 16;
    const uint32_t b_row = (uint32_t)((lane & 7) + ((lane >> 4) & 1) * 8) * ROWB;
    const uint32_t b_col = (uint32_t)((lane >> 3) & 1) * 16;
    const __half2 sc2 = __half2half2(__ushort_as_half((unsigned short)0x1000)); // 2^-11

    for (int c = 0; c < NC; c++) {
        cp_wait<0>();
        __syncthreads();
        if (c + 1 < NC)
            load_chunk(A, Wa, Wb, sbase, (c + 1) & 1, m0, n0, K, c + 1, tid);

        uint32_t st = sbase + (c & 1) * STAGE_SZ;
#pragma unroll
        for (int ks = 0; ks < 4; ks++) {
            uint32_t a[4][4];
#pragma unroll
            for (int mt = 0; mt < 4; mt++) {
                uint32_t addr = st + (uint32_t)(wm * 64 + mt * 16) * ROWB + a_row
                              + (uint32_t)ks * 32 + a_col;
                ldsm4(a[mt], addr);
            }
            // ---- term 0: A @ Wa ----
            {
                uint32_t bfr[4][2];
#pragma unroll
                for (int p = 0; p < 2; p++) {
                    uint32_t addr = st + A_SZ
                                  + (uint32_t)(wn * 32 + p * 16) * ROWB + b_row
                                  + (uint32_t)ks * 32 + b_col;
                    uint32_t r[4];
                    ldsm4(r, addr);
                    bfr[p * 2 + 0][0] = r[0]; bfr[p * 2 + 0][1] = r[1];
                    bfr[p * 2 + 1][0] = r[2]; bfr[p * 2 + 1][1] = r[3];
                }
#pragma unroll
                for (int mt = 0; mt < 4; mt++)
#pragma unroll
                    for (int nt = 0; nt < 4; nt++)
                        mma16816(acc[mt][nt], a[mt], bfr[nt]);
            }
            // scale A fragment: spikes 1 -> 2^-11 (exact)
#pragma unroll
            for (int mt = 0; mt < 4; mt++)
#pragma unroll
                for (int j = 0; j < 4; j++) {
                    __half2 v = *(__half2*)&a[mt][j];
                    v = __hmul2(v, sc2);
                    a[mt][j] = *(uint32_t*)&v;
                }
            // ---- term 1: (2^-11 * A) @ Wb ----
            {
                uint32_t bfr[4][2];
#pragma unroll
                for (int p = 0; p < 2; p++) {
                    uint32_t addr = st + A_SZ + W_SZ
                                  + (uint32_t)(wn * 32 + p * 16) * ROWB + b_row
                                  + (uint32_t)ks * 32 + b_col;
                    uint32_t r[4];
                    ldsm4(r, addr);
                    bfr[p * 2 + 0][0] = r[0]; bfr[p * 2 + 0][1] = r[1];
                    bfr[p * 2 + 1][0] = r[2]; bfr[p * 2 + 1][1] = r[3];
                }
#pragma unroll
                for (int mt = 0; mt < 4; mt++)
#pragma unroll
                    for (int nt = 0; nt < 4; nt++)
                        mma16816(acc[mt][nt], a[mt], bfr[nt]);
            }
        }
    }

    // ---- epilogue: stage tile in smem, LIF interior batches, spill boundary ----
    __syncthreads();
    float* ep = (float*)smem;                 // 128 x EPS floats = 66560 B
#pragma unroll
    for (int nt = 0; nt < 4; nt++) {
        const int col = wn * 32 + nt * 8 + (lane & 3) * 2;
#pragma unroll
        for (int mt = 0; mt < 4; mt++) {
            const int r0 = wm * 64 + mt * 16 + (lane >> 2);
            *(float2*)&ep[(size_t)r0 * EPS + col] =
                make_float2(acc[mt][nt][0], acc[mt][nt][1]);
            *(float2*)&ep[(size_t)(r0 + 8) * EPS + col] =
                make_float2(acc[mt][nt][2], acc[mt][nt][3]);
        }
    }
    __syncthreads();

    // interior batches, 2 columns per thread (independent LIF chains, same math)
    const int kb0 = (m0 + 9) / 10;
    const int kb1 = (m0 + 118) / 10;
    const int npair = (kb1 - kb0 + 1) * 64;
    for (int idx = tid; idx < npair; idx += 256) {
        const int k   = kb0 + (idx >> 6);
        const int col = (idx & 63) * 2;
        const float2 bz = *(const float2*)&bias[n0 + col];
        float mA = 0.0f, mB = 0.0f, sA = 0.0f, sB = 0.0f;
#pragma unroll
        for (int t = 0; t < T_STEPS; t++) {
            const int lr = k * 10 + t - m0;
            float2 cv = *(const float2*)&ep[(size_t)lr * EPS + col];
            float curA = __fadd_rn(cv.x, bz.x);
            float curB = __fadd_rn(cv.y, bz.y);
            float rA = (mA > 1.0f) ? 1.0f : 0.0f;
            float rB = (mB > 1.0f) ? 1.0f : 0.0f;
            mA = __fmul_rn(0.9f, mA); mA = __fadd_rn(mA, curA); mA = __fsub_rn(mA, rA);
            mB = __fmul_rn(0.9f, mB); mB = __fadd_rn(mB, curB); mB = __fsub_rn(mB, rB);
            bool spkA = (__fsub_rn(mA, 1.0f) > 0.0f);
            bool spkB = (__fsub_rn(mB, 1.0f) > 0.0f);
            if (MODE == 0) {
                uint32_t v = (spkA ? 0x3C00u : 0u) | (spkB ? 0x3C000000u : 0u);
                *(uint32_t*)(Sout + ((size_t)k * 10 + t) * N + (n0 + col)) = v;
            } else {
                if (spkA) sA += 1.0f;
                if (spkB) sB += 1.0f;
            }
        }
        if (MODE == 1)
            *(float2*)&SumOut[(size_t)k * 128 + col] = make_float2(sA, sB);
    }

    // boundary rows: spill cur (+bias) for fixup kernel, 2 cols per thread
    const int nb_lo = kb0 * 10 - m0;
    const int nb_hi = m0 + 128 - (kb1 + 1) * 10;
    const int nbp = (nb_lo + nb_hi) * 64;
    for (int idx = tid; idx < nbp; idx += 256) {
        const int j   = idx >> 6;
        const int col = (idx & 63) * 2;
        const int r   = (j < nb_lo) ? j : (128 - nb_hi + (j - nb_lo));
        float2 cv = *(const float2*)&ep[(size_t)r * EPS + col];
        float2 bz = *(const float2*)&bias[n0 + col];
        *(float2*)&Cur[(size_t)(m0 + r) * N + (n0 + col)] =
            make_float2(cv.x + bz.x, cv.y + bz.y);
    }
}

// ---------------- fixup: LIF for the 512 split batches only, 2 cols/thread ---
// split <=> k mod 64 in {12, 25, 38, 51}  (k = (j>>2)*64 + 12 + 13*(j&3))
#define N_SPLIT 512
template<int MODE>
__global__ void fixup_lif(const float* __restrict__ Cur, __half* __restrict__ Sout,
                          float* __restrict__ SumOut, int N) {
    int idx = blockIdx.x * 256 + threadIdx.x;
    const int half = N >> 1;
    if (idx >= N_SPLIT * half) return;
    int j = idx / half;
    int col = (idx - j * half) * 2;
    int k = (j >> 2) * 64 + 12 + 13 * (j & 3);
    float mA = 0.0f, mB = 0.0f, sA = 0.0f, sB = 0.0f;
#pragma unroll
    for (int t = 0; t < T_STEPS; t++) {
        float2 cv = *(const float2*)&Cur[((size_t)k * 10 + t) * N + col];
        float rA = (mA > 1.0f) ? 1.0f : 0.0f;
        float rB = (mB > 1.0f) ? 1.0f : 0.0f;
        mA = __fmul_rn(0.9f, mA); mA = __fadd_rn(mA, cv.x); mA = __fsub_rn(mA, rA);
        mB = __fmul_rn(0.9f, mB); mB = __fadd_rn(mB, cv.y); mB = __fsub_rn(mB, rB);
        bool spkA = (__fsub_rn(mA, 1.0f) > 0.0f);
        bool spkB = (__fsub_rn(mB, 1.0f) > 0.0f);
        if (MODE == 0) {
            uint32_t v = (spkA ? 0x3C00u : 0u) | (spkB ? 0x3C000000u : 0u);
            *(uint32_t*)(Sout + ((size_t)k * 10 + t) * N + col) = v;
        } else {
            if (spkA) sA += 1.0f;
            if (spkB) sB += 1.0f;
        }
    }
    if (MODE == 1)
        *(float2*)&SumOut[(size_t)k * 128 + col] = make_float2(sA, sB);
}

// ---------------- head: Z = S3sum @ W4^T + 10*b4, softmax ----------------
__global__ void head_kernel(const float* __restrict__ S3sum, const float* __restrict__ W4,
                            const float* __restrict__ b4, float* __restrict__ out) {
    int b = blockIdx.x * 256 + threadIdx.x;
    if (b >= B_SZ) return;
    float acc[N_OUT];
#pragma unroll
    for (int c = 0; c < N_OUT; c++) acc[c] = 10.0f * b4[c];
    const float* row = S3sum + (size_t)b * H3;
#pragma unroll 4
    for (int j = 0; j < H3; j++) {
        float x = row[j];
        if (x != 0.0f) {
#pragma unroll
            for (int c = 0; c < N_OUT; c++) acc[c] += x * __ldg(&W4[c * H3 + j]);
        }
    }
    float m = acc[0];
#pragma unroll
    for (int c = 1; c < N_OUT; c++) m = fmaxf(m, acc[c]);
    float sum = 0.0f, e[N_OUT];
#pragma unroll
    for (int c = 0; c < N_OUT; c++) { e[c] = expf(acc[c] - m); sum += e[c]; }
    float inv = 1.0f / sum;
#pragma unroll
    for (int c = 0; c < N_OUT; c++) out[(size_t)b * N_OUT + c] = e[c] * inv;
}

// ---------------- launch ----------------
extern "C" void kernel_launch(void* const* d_in, const int* in_sizes, int n_in,
                              void* d_out, int out_size) {
    const float* images = (const float*)d_in[0];
    const float* W1 = (const float*)d_in[1];
    const float* b1 = (const float*)d_in[2];
    const float* W2 = (const float*)d_in[3];
    const float* b2 = (const float*)d_in[4];
    const float* W3 = (const float*)d_in[5];
    const float* b3 = (const float*)d_in[6];
    const float* W4 = (const float*)d_in[7];
    const float* b4 = (const float*)d_in[8];
    float* out = (float*)d_out;

    __half *S, *s1, *s2, *W1s, *W2s, *W3s;
    float *cur1, *cur2, *cur3, *s3sum;
    cudaGetSymbolAddress((void**)&S,     g_S);
    cudaGetSymbolAddress((void**)&cur1,  g_cur1);
    cudaGetSymbolAddress((void**)&s1,    g_s1);
    cudaGetSymbolAddress((void**)&cur2,  g_cur2);
    cudaGetSymbolAddress((void**)&s2,    g_s2);
    cudaGetSymbolAddress((void**)&cur3,  g_cur3);
    cudaGetSymbolAddress((void**)&s3sum, g_s3sum);
    cudaGetSymbolAddress((void**)&W1s,   g_W1s);
    cudaGetSymbolAddress((void**)&W2s,   g_W2s);
    cudaGetSymbolAddress((void**)&W3s,   g_W3s);

    cudaFuncSetAttribute(gemm_lif<0>, cudaFuncAttributeMaxDynamicSharedMemorySize, GEMM_SMEM);
    cudaFuncSetAttribute(gemm_lif<1>, cudaFuncAttributeMaxDynamicSharedMemorySize, GEMM_SMEM);

    const size_t n1 = (size_t)H1 * D_IN, n2 = (size_t)H2 * H1, n3 = (size_t)H3 * H2;
    const int nsplit_tot = (int)(n1 + n2 + n3);
    split_w_all<<<(nsplit_tot + 255) / 256, 256>>>(W1, W2, W3, W1s, W2s, W3s);

    spikegen_kernel<<<(HALF_N / 4 + 255) / 256, 256>>>(images, S);

    gemm_lif<0><<<dim3(H1 / 128, M_TOT / 128), 256, GEMM_SMEM>>>(
        S, W1s, W1s + n1, b1, s1, nullptr, cur1, H1, D_IN);
    fixup_lif<0><<<(N_SPLIT * (H1 / 2) + 255) / 256, 256>>>(cur1, s1, nullptr, H1);

    gemm_lif<0><<<dim3(H2 / 128, M_TOT / 128), 256, GEMM_SMEM>>>(
        s1, W2s, W2s + n2, b2, s2, nullptr, cur2, H2, H1);
    fixup_lif<0><<<(N_SPLIT * (H2 / 2) + 255) / 256, 256>>>(cur2, s2, nullptr, H2);

    gemm_lif<1><<<dim3(H3 / 128, M_TOT / 128), 256, GEMM_SMEM>>>(
        s2, W3s, W3s + n3, b3, nullptr, s3sum, cur3, H3, H2);
    fixup_lif<1><<<(N_SPLIT * (H3 / 2) + 255) / 256, 256>>>(cur3, nullptr, s3sum, H3);

    head_kernel<<<(B_SZ + 255) / 256, 256>>>(s3sum, W4, b4, out);
}

// round 17
// speedup vs baseline: 1.1620x; 1.0155x over previous
#include <cuda_runtime.h>
#include <cuda_fp16.h>
#include <cstdint>

// ---------------- problem constants ----------------
#define T_STEPS 10
#define B_SZ    8192
#define D_IN    1024
#define H1      512
#define H2      256
#define H3      128
#define N_OUT   10
#define M_TOT   (T_STEPS * B_SZ)                          // 81920
#define HALF_N  ((uint32_t)(T_STEPS * B_SZ * D_IN / 2))   // 41,943,040

// b-major rows: m = b*10 + t
__device__ __half g_S   [(size_t)M_TOT * D_IN];           // 167 MB fp16 spikes
__device__ float  g_cur1[(size_t)M_TOT * H1];             // boundary rows only
__device__ __half g_s1  [(size_t)M_TOT * H1];
__device__ float  g_cur2[(size_t)M_TOT * H2];
__device__ __half g_s2  [(size_t)M_TOT * H2];
__device__ float  g_cur3[(size_t)M_TOT * H3];
__device__ float  g_s3sum[(size_t)B_SZ * H3];
__device__ __half g_W1s[2][(size_t)H1 * D_IN];
__device__ __half g_W2s[2][(size_t)H2 * H1];
__device__ __half g_W3s[2][(size_t)H3 * H2];

// ---------------- PTX helpers ----------------
__device__ __forceinline__ uint32_t smem_u32(const void* p) {
    uint32_t a;
    asm("{ .reg .u64 t; cvta.to.shared.u64 t, %1; cvt.u32.u64 %0, t; }" : "=r"(a) : "l"(p));
    return a;
}
__device__ __forceinline__ void cp16(uint32_t dst, const void* src) {
    asm volatile("cp.async.cg.shared.global [%0], [%1], 16;" :: "r"(dst), "l"(src) : "memory");
}
__device__ __forceinline__ void cp_commit() { asm volatile("cp.async.commit_group;" ::: "memory"); }
template<int N> __device__ __forceinline__ void cp_wait() {
    asm volatile("cp.async.wait_group %0;" :: "n"(N) : "memory");
}
__device__ __forceinline__ void ldsm4(uint32_t* r, uint32_t addr) {
    asm volatile("ldmatrix.sync.aligned.m8n8.x4.shared.b16 {%0,%1,%2,%3}, [%4];"
                 : "=r"(r[0]), "=r"(r[1]), "=r"(r[2]), "=r"(r[3]) : "r"(addr));
}
__device__ __forceinline__ void mma16816(float* d, const uint32_t* a, const uint32_t* b) {
    asm volatile(
        "mma.sync.aligned.m16n8k16.row.col.f32.f16.f16.f32 "
        "{%0,%1,%2,%3}, {%4,%5,%6,%7}, {%8,%9}, {%0,%1,%2,%3};"
        : "+f"(d[0]), "+f"(d[1]), "+f"(d[2]), "+f"(d[3])
        : "r"(a[0]), "r"(a[1]), "r"(a[2]), "r"(a[3]), "r"(b[0]), "r"(b[1]));
}

// ---------------- Threefry-2x32-20, key = (0, 42) ----------------
__device__ __forceinline__ uint32_t rotl32(uint32_t v, int r) {
    return (v << r) | (v >> (32 - r));
}
__device__ __forceinline__ void threefry_0_42(uint32_t x0, uint32_t x1,
                                              uint32_t& y0, uint32_t& y1) {
    const uint32_t k0 = 0u, k1 = 42u;
    const uint32_t k2 = k0 ^ k1 ^ 0x1BD11BDAu;
    x0 += k0; x1 += k1;
#define TF_RND(r) { x0 += x1; x1 = rotl32(x1, r); x1 ^= x0; }
    TF_RND(13) TF_RND(15) TF_RND(26) TF_RND(6)
    x0 += k1; x1 += k2 + 1u;
    TF_RND(17) TF_RND(29) TF_RND(16) TF_RND(24)
    x0 += k2; x1 += k0 + 2u;
    TF_RND(13) TF_RND(15) TF_RND(26) TF_RND(6)
    x0 += k0; x1 += k1 + 3u;
    TF_RND(17) TF_RND(29) TF_RND(16) TF_RND(24)
    x0 += k1; x1 += k2 + 4u;
    TF_RND(13) TF_RND(15) TF_RND(26) TF_RND(6)
    x0 += k2; x1 += k0 + 5u;
#undef TF_RND
    y0 = x0; y1 = x1;
}

// Exact integer spike test: (y>>9)*2^-23 < img  <=>  (y>>9) < ceil(img*2^23).
__device__ __forceinline__ uint32_t thr_of(float img) {
    return __float2uint_ru(img * 8388608.0f);
}

// ---------------- merged prep kernel: weight split + spikegen ----------------
// Blocks [0, SWB): 2-way fp16 weight split (scheduled first; GEMM1 needs W).
// Blocks [SWB, ...): spikegen, 8 counters per thread. b-major spike store:
// row = b*10 + t; counter pair (i, i+HALF) = (t, t+5) of the SAME (b, d).
// 8 adjacent counters share (t, b, base); d = 0 mod 8 -> two aligned 16B stores.
#define SW_N   (H1 * D_IN + H2 * H1 + H3 * H2)   // 688128
#define SWB    (SW_N / 256)                       // 2688
#define SPIKE_BLOCKS ((int)(HALF_N / 8 / 256))    // 20480

__global__ void prep_kernel(const float* __restrict__ images, __half* __restrict__ S,
                            const float* __restrict__ W1, const float* __restrict__ W2,
                            const float* __restrict__ W3,
                            __half* __restrict__ W1s, __half* __restrict__ W2s,
                            __half* __restrict__ W3s) {
    const int n1 = H1 * D_IN, n2 = H2 * H1, n3 = H3 * H2;
    if (blockIdx.x < SWB) {
        int i = blockIdx.x * 256 + threadIdx.x;
        const float* W; __half *a, *b; int k;
        if (i < n1)           { W = W1; a = W1s; b = W1s + n1; k = i; }
        else if (i < n1 + n2) { W = W2; a = W2s; b = W2s + n2; k = i - n1; }
        else                  { W = W3; a = W3s; b = W3s + n3; k = i - n1 - n2; }
        float w = W[k];
        __half h = __float2half(w);
        float r = w - __half2float(h);
        a[k] = h;
        b[k] = __float2half(r * 2048.0f);   // w ~ a + 2^-11 * b, err <= 2^-23*|w|
        return;
    }
    uint32_t j = (uint32_t)(blockIdx.x - SWB) * 256u + threadIdx.x;
    uint32_t i = j * 8u;                     // exact cover: SPIKE_BLOCKS*256*8 == HALF_N
    uint32_t t = i >> 23;                    // B*D = 2^23
    uint32_t r = i & 0x7FFFFFu;              // multiple of 8
    float4 im0 = *(const float4*)(images + r);
    float4 im1 = *(const float4*)(images + r + 4);
    uint32_t th[8] = { thr_of(im0.x), thr_of(im0.y), thr_of(im0.z), thr_of(im0.w),
                       thr_of(im1.x), thr_of(im1.y), thr_of(im1.z), thr_of(im1.w) };
    uint32_t lo[4] = {0u, 0u, 0u, 0u};
    uint32_t hi[4] = {0u, 0u, 0u, 0u};
#pragma unroll
    for (int q = 0; q < 8; q++) {
        uint32_t y0, y1;
        threefry_0_42(i + q, i + q + HALF_N, y0, y1);
        uint32_t sh = (uint32_t)(q & 1) * 16u;
        if ((y0 >> 9) < th[q]) lo[q >> 1] |= (0x3C00u << sh);
        if ((y1 >> 9) < th[q]) hi[q >> 1] |= (0x3C00u << sh);
    }
    uint32_t b = r >> 10;
    uint32_t d = r & 1023u;
    size_t base = ((size_t)(b * 10u) << 10) + d;
    *(uint4*)(S + base + ((size_t)t << 10))        = make_uint4(lo[0], lo[1], lo[2], lo[3]);
    *(uint4*)(S + base + ((size_t)(t + 5u) << 10)) = make_uint4(hi[0], hi[1], hi[2], hi[3]);
}

// ---------------- mma.sync GEMM + fused LIF epilogue (locked core) -----------
#define ROWB 144
#define A_SZ   (128 * ROWB)                 // 18432 B
#define W_SZ   (128 * ROWB)                 // 18432 B
#define STAGE_SZ (A_SZ + 2 * W_SZ)          // 55296 B
#define GEMM_SMEM (2 * STAGE_SZ)            // 110592 B
#define EPS 130                             // epilogue smem stride (floats)

__device__ __forceinline__ void load_chunk(
    const __half* __restrict__ A, const __half* __restrict__ Wa,
    const __half* __restrict__ Wb, uint32_t sbase, int stage,
    int m0, int n0, int K, int c, int tid)
{
    uint32_t st = sbase + stage * STAGE_SZ;
    const int k0 = c * 64;
    const __half* Ab = A + (size_t)m0 * K + k0;
#pragma unroll
    for (int i = 0; i < 4; i++) {
        int idx = i * 256 + tid;
        int row = idx >> 3, q = idx & 7;
        cp16(st + (uint32_t)(row * ROWB + q * 16), Ab + (size_t)row * K + q * 8);
    }
    const __half* const Ws[2] = {Wa, Wb};
#pragma unroll
    for (int s = 0; s < 2; s++) {
        const __half* Wp = Ws[s] + (size_t)n0 * K + k0;
        uint32_t bs = st + A_SZ + s * W_SZ;
#pragma unroll
        for (int i = 0; i < 4; i++) {
            int idx = i * 256 + tid;
            int row = idx >> 3, q = idx & 7;
            cp16(bs + (uint32_t)(row * ROWB + q * 16), Wp + (size_t)row * K + q * 8);
        }
    }
    cp_commit();
}

template<int MODE>  // 0: LIF -> fp16 spikes; 1: LIF -> float spike sum
__global__ __launch_bounds__(256, 2)
void gemm_lif(const __half* __restrict__ A,
              const __half* __restrict__ Wa,
              const __half* __restrict__ Wb,
              const float* __restrict__ bias,
              __half* __restrict__ Sout,
              float* __restrict__ SumOut,
              float* __restrict__ Cur,
              int N, int K)
{
    extern __shared__ char smem[];
    const uint32_t sbase = smem_u32(smem);
    const int tid  = threadIdx.x;
    const int warp = tid >> 5;
    const int lane = tid & 31;
    const int wm = warp >> 2;                 // m offset wm*64
    const int wn = warp & 3;                  // n offset wn*32
    const int m0 = blockIdx.y * 128;
    const int n0 = blockIdx.x * 128;
    const int NC = K >> 6;

    float acc[4][4][4];
#pragma unroll
    for (int mt = 0; mt < 4; mt++)
#pragma unroll
        for (int nt = 0; nt < 4; nt++)
#pragma unroll
            for (int r = 0; r < 4; r++) acc[mt][nt][r] = 0.0f;

    load_chunk(A, Wa, Wb, sbase, 0, m0, n0, K, 0, tid);

    const uint32_t a_row = (uint32_t)(lane & 15) * ROWB;
    const uint32_t a_col = (uint32_t)(lane >> 4) * 16;
    const uint32_t b_row = (uint32_t)((lane & 7) + ((lane >> 4) & 1) * 8) * ROWB;
    const uint32_t b_col = (uint32_t)((lane >> 3) & 1) * 16;
    const __half2 sc2 = __half2half2(__ushort_as_half((unsigned short)0x1000)); // 2^-11

    for (int c = 0; c < NC; c++) {
        cp_wait<0>();
        __syncthreads();
        if (c + 1 < NC)
            load_chunk(A, Wa, Wb, sbase, (c + 1) & 1, m0, n0, K, c + 1, tid);

        uint32_t st = sbase + (c & 1) * STAGE_SZ;
#pragma unroll
        for (int ks = 0; ks < 4; ks++) {
            uint32_t a[4][4];
#pragma unroll
            for (int mt = 0; mt < 4; mt++) {
                uint32_t addr = st + (uint32_t)(wm * 64 + mt * 16) * ROWB + a_row
                              + (uint32_t)ks * 32 + a_col;
                ldsm4(a[mt], addr);
            }
            // ---- term 0: A @ Wa ----
            {
                uint32_t bfr[4][2];
#pragma unroll
                for (int p = 0; p < 2; p++) {
                    uint32_t addr = st + A_SZ
                                  + (uint32_t)(wn * 32 + p * 16) * ROWB + b_row
                                  + (uint32_t)ks * 32 + b_col;
                    uint32_t r[4];
                    ldsm4(r, addr);
                    bfr[p * 2 + 0][0] = r[0]; bfr[p * 2 + 0][1] = r[1];
                    bfr[p * 2 + 1][0] = r[2]; bfr[p * 2 + 1][1] = r[3];
                }
#pragma unroll
                for (int mt = 0; mt < 4; mt++)
#pragma unroll
                    for (int nt = 0; nt < 4; nt++)
                        mma16816(acc[mt][nt], a[mt], bfr[nt]);
            }
            // scale A fragment: spikes 1 -> 2^-11 (exact)
#pragma unroll
            for (int mt = 0; mt < 4; mt++)
#pragma unroll
                for (int j = 0; j < 4; j++) {
                    __half2 v = *(__half2*)&a[mt][j];
                    v = __hmul2(v, sc2);
                    a[mt][j] = *(uint32_t*)&v;
                }
            // ---- term 1: (2^-11 * A) @ Wb ----
            {
                uint32_t bfr[4][2];
#pragma unroll
                for (int p = 0; p < 2; p++) {
                    uint32_t addr = st + A_SZ + W_SZ
                                  + (uint32_t)(wn * 32 + p * 16) * ROWB + b_row
                                  + (uint32_t)ks * 32 + b_col;
                    uint32_t r[4];
                    ldsm4(r, addr);
                    bfr[p * 2 + 0][0] = r[0]; bfr[p * 2 + 0][1] = r[1];
                    bfr[p * 2 + 1][0] = r[2]; bfr[p * 2 + 1][1] = r[3];
                }
#pragma unroll
                for (int mt = 0; mt < 4; mt++)
#pragma unroll
                    for (int nt = 0; nt < 4; nt++)
                        mma16816(acc[mt][nt], a[mt], bfr[nt]);
            }
        }
    }

    // ---- epilogue: stage tile in smem, LIF interior batches, spill boundary ----
    __syncthreads();
    float* ep = (float*)smem;                 // 128 x EPS floats = 66560 B
#pragma unroll
    for (int nt = 0; nt < 4; nt++) {
        const int col = wn * 32 + nt * 8 + (lane & 3) * 2;
#pragma unroll
        for (int mt = 0; mt < 4; mt++) {
            const int r0 = wm * 64 + mt * 16 + (lane >> 2);
            *(float2*)&ep[(size_t)r0 * EPS + col] =
                make_float2(acc[mt][nt][0], acc[mt][nt][1]);
            *(float2*)&ep[(size_t)(r0 + 8) * EPS + col] =
                make_float2(acc[mt][nt][2], acc[mt][nt][3]);
        }
    }
    __syncthreads();

    // interior batches, 2 columns per thread (independent LIF chains, same math)
    const int kb0 = (m0 + 9) / 10;
    const int kb1 = (m0 + 118) / 10;
    const int npair = (kb1 - kb0 + 1) * 64;
    for (int idx = tid; idx < npair; idx += 256) {
        const int k   = kb0 + (idx >> 6);
        const int col = (idx & 63) * 2;
        const float2 bz = *(const float2*)&bias[n0 + col];
        float mA = 0.0f, mB = 0.0f, sA = 0.0f, sB = 0.0f;
#pragma unroll
        for (int t = 0; t < T_STEPS; t++) {
            const int lr = k * 10 + t - m0;
            float2 cv = *(const float2*)&ep[(size_t)lr * EPS + col];
            float curA = __fadd_rn(cv.x, bz.x);
            float curB = __fadd_rn(cv.y, bz.y);
            float rA = (mA > 1.0f) ? 1.0f : 0.0f;
            float rB = (mB > 1.0f) ? 1.0f : 0.0f;
            mA = __fmul_rn(0.9f, mA); mA = __fadd_rn(mA, curA); mA = __fsub_rn(mA, rA);
            mB = __fmul_rn(0.9f, mB); mB = __fadd_rn(mB, curB); mB = __fsub_rn(mB, rB);
            bool spkA = (__fsub_rn(mA, 1.0f) > 0.0f);
            bool spkB = (__fsub_rn(mB, 1.0f) > 0.0f);
            if (MODE == 0) {
                uint32_t v = (spkA ? 0x3C00u : 0u) | (spkB ? 0x3C000000u : 0u);
                *(uint32_t*)(Sout + ((size_t)k * 10 + t) * N + (n0 + col)) = v;
            } else {
                if (spkA) sA += 1.0f;
                if (spkB) sB += 1.0f;
            }
        }
        if (MODE == 1)
            *(float2*)&SumOut[(size_t)k * 128 + col] = make_float2(sA, sB);
    }

    // boundary rows: spill cur (+bias) for fixup kernel, 2 cols per thread
    const int nb_lo = kb0 * 10 - m0;
    const int nb_hi = m0 + 128 - (kb1 + 1) * 10;
    const int nbp = (nb_lo + nb_hi) * 64;
    for (int idx = tid; idx < nbp; idx += 256) {
        const int j   = idx >> 6;
        const int col = (idx & 63) * 2;
        const int r   = (j < nb_lo) ? j : (128 - nb_hi + (j - nb_lo));
        float2 cv = *(const float2*)&ep[(size_t)r * EPS + col];
        float2 bz = *(const float2*)&bias[n0 + col];
        *(float2*)&Cur[(size_t)(m0 + r) * N + (n0 + col)] =
            make_float2(cv.x + bz.x, cv.y + bz.y);
    }
}

// ---------------- fixup: LIF for the 512 split batches only, 2 cols/thread ---
// split <=> k mod 64 in {12, 25, 38, 51}  (k = (j>>2)*64 + 12 + 13*(j&3))
#define N_SPLIT 512
template<int MODE>
__global__ void fixup_lif(const float* __restrict__ Cur, __half* __restrict__ Sout,
                          float* __restrict__ SumOut, int N) {
    int idx = blockIdx.x * 256 + threadIdx.x;
    const int half = N >> 1;
    if (idx >= N_SPLIT * half) return;
    int j = idx / half;
    int col = (idx - j * half) * 2;
    int k = (j >> 2) * 64 + 12 + 13 * (j & 3);
    float mA = 0.0f, mB = 0.0f, sA = 0.0f, sB = 0.0f;
#pragma unroll
    for (int t = 0; t < T_STEPS; t++) {
        float2 cv = *(const float2*)&Cur[((size_t)k * 10 + t) * N + col];
        float rA = (mA > 1.0f) ? 1.0f : 0.0f;
        float rB = (mB > 1.0f) ? 1.0f : 0.0f;
        mA = __fmul_rn(0.9f, mA); mA = __fadd_rn(mA, cv.x); mA = __fsub_rn(mA, rA);
        mB = __fmul_rn(0.9f, mB); mB = __fadd_rn(mB, cv.y); mB = __fsub_rn(mB, rB);
        bool spkA = (__fsub_rn(mA, 1.0f) > 0.0f);
        bool spkB = (__fsub_rn(mB, 1.0f) > 0.0f);
        if (MODE == 0) {
            uint32_t v = (spkA ? 0x3C00u : 0u) | (spkB ? 0x3C000000u : 0u);
            *(uint32_t*)(Sout + ((size_t)k * 10 + t) * N + col) = v;
        } else {
            if (spkA) sA += 1.0f;
            if (spkB) sB += 1.0f;
        }
    }
    if (MODE == 1)
        *(float2*)&SumOut[(size_t)k * 128 + col] = make_float2(sA, sB);
}

// ---------------- head: Z = S3sum @ W4^T + 10*b4, softmax ----------------
__global__ void head_kernel(const float* __restrict__ S3sum, const float* __restrict__ W4,
                            const float* __restrict__ b4, float* __restrict__ out) {
    int b = blockIdx.x * 256 + threadIdx.x;
    if (b >= B_SZ) return;
    float acc[N_OUT];
#pragma unroll
    for (int c = 0; c < N_OUT; c++) acc[c] = 10.0f * b4[c];
    const float* row = S3sum + (size_t)b * H3;
#pragma unroll 4
    for (int j = 0; j < H3; j++) {
        float x = row[j];
        if (x != 0.0f) {
#pragma unroll
            for (int c = 0; c < N_OUT; c++) acc[c] += x * __ldg(&W4[c * H3 + j]);
        }
    }
    float m = acc[0];
#pragma unroll
    for (int c = 1; c < N_OUT; c++) m = fmaxf(m, acc[c]);
    float sum = 0.0f, e[N_OUT];
#pragma unroll
    for (int c = 0; c < N_OUT; c++) { e[c] = expf(acc[c] - m); sum += e[c]; }
    float inv = 1.0f / sum;
#pragma unroll
    for (int c = 0; c < N_OUT; c++) out[(size_t)b * N_OUT + c] = e[c] * inv;
}

// ---------------- launch ----------------
extern "C" void kernel_launch(void* const* d_in, const int* in_sizes, int n_in,
                              void* d_out, int out_size) {
    const float* images = (const float*)d_in[0];
    const float* W1 = (const float*)d_in[1];
    const float* b1 = (const float*)d_in[2];
    const float* W2 = (const float*)d_in[3];
    const float* b2 = (const float*)d_in[4];
    const float* W3 = (const float*)d_in[5];
    const float* b3 = (const float*)d_in[6];
    const float* W4 = (const float*)d_in[7];
    const float* b4 = (const float*)d_in[8];
    float* out = (float*)d_out;

    __half *S, *s1, *s2, *W1s, *W2s, *W3s;
    float *cur1, *cur2, *cur3, *s3sum;
    cudaGetSymbolAddress((void**)&S,     g_S);
    cudaGetSymbolAddress((void**)&cur1,  g_cur1);
    cudaGetSymbolAddress((void**)&s1,    g_s1);
    cudaGetSymbolAddress((void**)&cur2,  g_cur2);
    cudaGetSymbolAddress((void**)&s2,    g_s2);
    cudaGetSymbolAddress((void**)&cur3,  g_cur3);
    cudaGetSymbolAddress((void**)&s3sum, g_s3sum);
    cudaGetSymbolAddress((void**)&W1s,   g_W1s);
    cudaGetSymbolAddress((void**)&W2s,   g_W2s);
    cudaGetSymbolAddress((void**)&W3s,   g_W3s);

    cudaFuncSetAttribute(gemm_lif<0>, cudaFuncAttributeMaxDynamicSharedMemorySize, GEMM_SMEM);
    cudaFuncSetAttribute(gemm_lif<1>, cudaFuncAttributeMaxDynamicSharedMemorySize, GEMM_SMEM);

    const size_t n1 = (size_t)H1 * D_IN, n2 = (size_t)H2 * H1, n3 = (size_t)H3 * H2;

    // launch 0: weight split (blocks 0..SWB-1) + spikegen (rest), merged
    prep_kernel<<<SWB + SPIKE_BLOCKS, 256>>>(images, S, W1, W2, W3, W1s, W2s, W3s);

    // launch 1, 2
    gemm_lif<0><<<dim3(H1 / 128, M_TOT / 128), 256, GEMM_SMEM>>>(
        S, W1s, W1s + n1, b1, s1, nullptr, cur1, H1, D_IN);
    fixup_lif<0><<<(N_SPLIT * (H1 / 2) + 255) / 256, 256>>>(cur1, s1, nullptr, H1);

    // launch 3, 4
    gemm_lif<0><<<dim3(H2 / 128, M_TOT / 128), 256, GEMM_SMEM>>>(
        s1, W2s, W2s + n2, b2, s2, nullptr, cur2, H2, H1);
    fixup_lif<0><<<(N_SPLIT * (H2 / 2) + 255) / 256, 256>>>(cur2, s2, nullptr, H2);

    // launch 5 (ncu -s 5 -c 1 captures this gemm), 6
    gemm_lif<1><<<dim3(H3 / 128, M_TOT / 128), 256, GEMM_SMEM>>>(
        s2, W3s, W3s + n3, b3, nullptr, s3sum, cur3, H3, H2);
    fixup_lif<1><<<(N_SPLIT * (H3 / 2) + 255) / 256, 256>>>(cur3, nullptr, s3sum, H3);

    // launch 7
    head_kernel<<<(B_SZ + 255) / 256, 256>>>(s3sum, W4, b4, out);
}